// round 14
// baseline (speedup 1.0000x reference)
#include <cuda_runtime.h>
#include <cuda_bf16.h>
#include <math.h>
#include <stdint.h>

#define E_EDGES 100000
#define S_MEM   16
#define D_DIM   128
#define C_CLS   6
#define M_IND   4
#define ROWS    128
#define NTH     512
#define SCALE_INV 0.08838834764831845f

// SMEM byte offsets
#define OFF_XH  0
#define OFF_XL  32768
#define OFF_WH  65536
#define OFF_WL  98304
#define OFF_SF  131072                 // f32 [128][132]
#define SF_STR  132
#define OFF_SSM (OFF_SF + 128*SF_STR*4)    // f32 [32][132]
#define OFF_BIAS (OFF_SSM + 32*SF_STR*4)   // f32 [6][128]
#define OFF_IQ  (OFF_BIAS + 6*128*4)       // f32 [512]
#define OFF_IQB (OFF_IQ + 2048)            // f32 [16]
#define OFF_WOUT (OFF_IQB + 64)            // f32 [776]
#define OFF_SCR (OFF_WOUT + 3104)          // f32 [2048]
#define SMEM_TOTAL (OFF_SCR + 8192)        // 232032 <= 232448

__device__ __align__(16) float g_Iq[M_IND * D_DIM];
__device__ __align__(16) float g_Iqb[16];
__device__ __align__(16) __nv_bfloat16 g_WH[7][16384];
__device__ __align__(16) __nv_bfloat16 g_WL[7][16384];

__host__ __device__ __forceinline__ int imgoff(int r, int c) {
    return r * 256 + (((c >> 3) ^ (r & 7)) << 4) + ((c & 7) << 1);
}

__device__ __forceinline__ uint32_t cvta_s(const void* p) {
    uint32_t a;
    asm("{ .reg .u64 t; cvta.to.shared.u64 t, %1; cvt.u32.u64 %0, t; }" : "=r"(a) : "l"(p));
    return a;
}
__device__ __forceinline__ void ldsm4(uint32_t* a, uint32_t addr) {
    asm volatile("ldmatrix.sync.aligned.m8n8.x4.shared.b16 {%0,%1,%2,%3}, [%4];"
        : "=r"(a[0]), "=r"(a[1]), "=r"(a[2]), "=r"(a[3]) : "r"(addr));
}
__device__ __forceinline__ void mma16816(float* c, const uint32_t* a, uint32_t b0, uint32_t b1) {
    asm volatile("mma.sync.aligned.m16n8k16.row.col.f32.bf16.bf16.f32 "
        "{%0,%1,%2,%3}, {%4,%5,%6,%7}, {%8,%9}, {%0,%1,%2,%3};"
        : "+f"(c[0]), "+f"(c[1]), "+f"(c[2]), "+f"(c[3])
        : "r"(a[0]), "r"(a[1]), "r"(a[2]), "r"(a[3]), "r"(b0), "r"(b1));
}
__device__ __forceinline__ void cp16(uint32_t dst, const void* src) {
    asm volatile("cp.async.cg.shared.global [%0], [%1], 16;" :: "r"(dst), "l"(src) : "memory");
}
__device__ __forceinline__ void cp_commit() { asm volatile("cp.async.commit_group;" ::: "memory"); }
__device__ __forceinline__ void cp_wait()   { asm volatile("cp.async.wait_group 0;" ::: "memory"); }

__device__ __forceinline__ uint32_t bf2bits(float a, float b) {
    __nv_bfloat162 p; p.x = __float2bfloat16(a); p.y = __float2bfloat16(b);
    return *(uint32_t*)&p;
}
__device__ __forceinline__ void img_st4(char* sm, int r, int c, float4 v) {
    int i = imgoff(r, c);
    float hx = __bfloat162float(__float2bfloat16(v.x));
    float hy = __bfloat162float(__float2bfloat16(v.y));
    float hz = __bfloat162float(__float2bfloat16(v.z));
    float hw = __bfloat162float(__float2bfloat16(v.w));
    uint2 hh, ll;
    hh.x = bf2bits(v.x, v.y);      hh.y = bf2bits(v.z, v.w);
    ll.x = bf2bits(v.x - hx, v.y - hy);
    ll.y = bf2bits(v.z - hz, v.w - hw);
    *(uint2*)(sm + OFF_XH + i) = hh;
    *(uint2*)(sm + OFF_XL + i) = ll;
}

// ---------------- prologs ----------------
__global__ void iq_kernel(const float* __restrict__ I, const float* __restrict__ Wq,
                          const float* __restrict__ bq) {
    int idx = blockIdx.x * blockDim.x + threadIdx.x;
    if (idx >= M_IND * D_DIM) return;
    int qi = idx / D_DIM, d = idx % D_DIM;
    float acc = bq[d];
    for (int k = 0; k < D_DIM; k++) acc += I[qi * D_DIM + k] * Wq[k * D_DIM + d];
    g_Iq[idx] = acc;
}
__global__ void iqb_kernel(const float* __restrict__ bk0) {
    int t = threadIdx.x;
    if (t < 16) {
        int qi = t >> 2, h = t & 3;
        float s = 0.f;
        for (int j = 0; j < 32; j++) s += g_Iq[qi * 128 + h * 32 + j] * bk0[h * 32 + j];
        g_Iqb[t] = s;
    }
}
__global__ void wconv_kernel(const float* W0, const float* W1, const float* W2, const float* W3,
                             const float* W4, const float* W5, const float* W6) {
    const float* W;
    int m = blockIdx.x;
    switch (m) { case 0: W = W0; break; case 1: W = W1; break; case 2: W = W2; break;
                 case 3: W = W3; break; case 4: W = W4; break; case 5: W = W5; break;
                 default: W = W6; }
    for (int i = threadIdx.x; i < 16384; i += blockDim.x) {
        int n = i >> 7, k = i & 127;
        float w = W[k * 128 + n];
        __nv_bfloat16 h = __float2bfloat16(w);
        int idx = n * 128 + (((k >> 3) ^ (n & 7)) << 3) + (k & 7);
        g_WH[m][idx] = h;
        g_WL[m][idx] = __float2bfloat16(w - __bfloat162float(h));
    }
}

__device__ __forceinline__ void lw_issue(char* sm, uint32_t sb, int widx, int tid) {
    const char* gh = (const char*)g_WH[widx];
    const char* gl = (const char*)g_WL[widx];
    uint32_t dh = sb + OFF_WH, dl = sb + OFF_WL;
#pragma unroll
    for (int i = 0; i < 4; i++) {
        int off = (tid + i * 512) * 16;
        cp16(dh + off, gh + off);
        cp16(dl + off, gl + off);
    }
    cp_commit();
}

// 128x128x128 GEMM, 16 warps: 4 rowgroups (32 rows) x 4 colgroups (32 cols)
__device__ __forceinline__ void gemm128(uint32_t xh, uint32_t xl, uint32_t wh, uint32_t wl,
                                        int wid, int lane, float acc[2][4][4]) {
    const int rg = wid >> 2, cg = wid & 3;
    const int lr = lane & 15, lh = lane >> 4;
    const int bn = (lane & 7) + ((lane >> 4) << 3);
    const int bh2 = (lane >> 3) & 1;
#pragma unroll
    for (int ks = 0; ks < 8; ks++) {
        uint32_t ah[2][4], al[2][4];
#pragma unroll
        for (int rt = 0; rt < 2; rt++) {
            int r = rg * 32 + rt * 16 + lr;
            uint32_t off = (uint32_t)(r * 256 + (((ks * 2 + lh) ^ (r & 7)) << 4));
            ldsm4(ah[rt], xh + off);
            ldsm4(al[rt], xl + off);
        }
#pragma unroll
        for (int ntp = 0; ntp < 2; ntp++) {
            int n = cg * 32 + ntp * 16 + bn;
            uint32_t boff = (uint32_t)(n * 256 + (((ks * 2 + bh2) ^ (n & 7)) << 4));
            uint32_t bh[4], bl[4];
            ldsm4(bh, wh + boff);
            ldsm4(bl, wl + boff);
#pragma unroll
            for (int rt = 0; rt < 2; rt++) {
                mma16816(acc[rt][2 * ntp],     ah[rt], bh[0], bh[1]);
                mma16816(acc[rt][2 * ntp],     al[rt], bh[0], bh[1]);
                mma16816(acc[rt][2 * ntp],     ah[rt], bl[0], bl[1]);
                mma16816(acc[rt][2 * ntp + 1], ah[rt], bh[2], bh[3]);
                mma16816(acc[rt][2 * ntp + 1], al[rt], bh[2], bh[3]);
                mma16816(acc[rt][2 * ntp + 1], ah[rt], bl[2], bl[3]);
            }
        }
    }
}

// 32x128x128 GEMM, 16 warps: rowtile wid>>3 (16 rows), colgroup wid&7 (16 cols)
__device__ __forceinline__ void gemm32(uint32_t xh, uint32_t xl, uint32_t wh, uint32_t wl,
                                       int wid, int lane, float acc[2][4]) {
    const int rt = wid >> 3, cg8 = wid & 7;
    const int lr = lane & 15, lh = lane >> 4;
    const int bn = (lane & 7) + ((lane >> 4) << 3);
    const int bh2 = (lane >> 3) & 1;
#pragma unroll
    for (int ks = 0; ks < 8; ks++) {
        uint32_t ah[4], al[4];
        int r = rt * 16 + lr;
        uint32_t off = (uint32_t)(r * 256 + (((ks * 2 + lh) ^ (r & 7)) << 4));
        ldsm4(ah, xh + off);
        ldsm4(al, xl + off);
        int n = cg8 * 16 + bn;
        uint32_t boff = (uint32_t)(n * 256 + (((ks * 2 + bh2) ^ (n & 7)) << 4));
        uint32_t bh[4], bl[4];
        ldsm4(bh, wh + boff);
        ldsm4(bl, wl + boff);
        mma16816(acc[0], ah, bh[0], bh[1]);
        mma16816(acc[0], al, bh[0], bh[1]);
        mma16816(acc[0], ah, bl[0], bl[1]);
        mma16816(acc[1], ah, bh[2], bh[3]);
        mma16816(acc[1], al, bh[2], bh[3]);
        mma16816(acc[1], ah, bl[2], bl[3]);
    }
}

extern "C" __global__ void __launch_bounds__(NTH, 1)
whatsnet_mma(const float* __restrict__ vfeat, const int* __restrict__ member_idx,
             const int* __restrict__ labels,
             const float* __restrict__ Wout, const float* __restrict__ bout,
             const float* __restrict__ bv0, const float* __restrict__ bo0,
             const float* __restrict__ bq1, const float* __restrict__ bk1,
             const float* __restrict__ bv1, const float* __restrict__ bo1,
             float* __restrict__ out, int n_nodes, long long out_capacity)
{
    extern __shared__ char sm[];
    const int tid = threadIdx.x;
    const int wid = tid >> 5, lane = tid & 31;
    const int rowbase = blockIdx.x * ROWS;
    const uint32_t sb = cvta_s(sm);
    const uint32_t xh = sb + OFF_XH, xl = sb + OFF_XL;
    const uint32_t wh = sb + OFF_WH, wl = sb + OFF_WL;

    float* sF   = (float*)(sm + OFF_SF);
    float* sSm  = (float*)(sm + OFF_SSM);     // O0; later V1f
    float* sK1  = (float*)(sm + OFF_XH + 8704);  // K1f scratch, disjoint from image rows 0..31
    float* sBias= (float*)(sm + OFF_BIAS);
    float* sIq  = (float*)(sm + OFF_IQ);
    float* sIqb = (float*)(sm + OFF_IQB);
    float* sWo  = (float*)(sm + OFF_WOUT);
    float* sScr = (float*)(sm + OFF_SCR);

    // constants
    if (tid < 128) {
        sBias[0 * 128 + tid] = bv0[tid];
        sBias[1 * 128 + tid] = bo0[tid];
        sBias[2 * 128 + tid] = bq1[tid];
        sBias[3 * 128 + tid] = bk1[tid];
        sBias[4 * 128 + tid] = bv1[tid];
        sBias[5 * 128 + tid] = bo1[tid];
    }
    if (tid < 512) sIq[tid] = g_Iq[tid];
    if (tid < 16) sIqb[tid] = g_Iqb[tid];
    for (int i = tid; i < 768; i += NTH) sWo[i] = Wout[i];
    if (tid < 6) sWo[768 + tid] = bout[tid];

    lw_issue(sm, sb, 0, tid);

    // gather -> X images
    for (int r = wid; r < ROWS; r += 16) {
        int n = member_idx[rowbase + r];
        if (n < 0) n = 0;
        if (n >= n_nodes) n = n_nodes - 1;
        float4 v = *(const float4*)(vfeat + (size_t)n * D_DIM + lane * 4);
        img_st4(sm, r, lane * 4, v);
    }
    cp_wait();
    __syncthreads();

    const int l4 = lane >> 2, c2 = (lane & 3) * 2;
    const int rg = wid >> 2, cg = wid & 3;

    float acc[2][4][4];
    float acc32[2][4];

    // ===== K0 = X@Wk0 -> sF =====
#pragma unroll
    for (int i = 0; i < 2; i++)
#pragma unroll
        for (int j = 0; j < 4; j++)
#pragma unroll
            for (int q = 0; q < 4; q++) acc[i][j][q] = 0.f;
    gemm128(xh, xl, wh, wl, wid, lane, acc);
#pragma unroll
    for (int rt = 0; rt < 2; rt++) {
        int r = rg * 32 + rt * 16 + l4;
#pragma unroll
        for (int nt = 0; nt < 4; nt++) {
            int c = cg * 32 + nt * 8 + c2;
            sF[r * SF_STR + c]       = acc[rt][nt][0];
            sF[r * SF_STR + c + 1]   = acc[rt][nt][1];
            sF[(r + 8) * SF_STR + c]     = acc[rt][nt][2];
            sF[(r + 8) * SF_STR + c + 1] = acc[rt][nt][3];
        }
    }
    __syncthreads();
    lw_issue(sm, sb, 1, tid);

    // scores0
#pragma unroll
    for (int it = 0; it < 4; it++) {
        int idx = tid + it * 512;
        int s = idx & 15, qi = (idx >> 4) & 3, h = (idx >> 6) & 3, e = idx >> 8;
        const float4* qv = (const float4*)&sIq[qi * 128 + h * 32];
        const float4* kv = (const float4*)&sF[(e * 16 + s) * SF_STR + h * 32];
        float dot = sIqb[qi * 4 + h];
#pragma unroll
        for (int d4 = 0; d4 < 8; d4++) {
            float4 q = qv[d4], k = kv[d4];
            dot += q.x * k.x + q.y * k.y + q.z * k.z + q.w * k.w;
        }
        sScr[idx] = dot * SCALE_INV;
    }
    cp_wait();
    __syncthreads();

    // ===== V0 = X@Wv0 + bv0 -> sF ; softmax0 =====
#pragma unroll
    for (int i = 0; i < 2; i++)
#pragma unroll
        for (int j = 0; j < 4; j++)
#pragma unroll
            for (int q = 0; q < 4; q++) acc[i][j][q] = 0.f;
    gemm128(xh, xl, wh, wl, wid, lane, acc);
#pragma unroll
    for (int rt = 0; rt < 2; rt++) {
        int r = rg * 32 + rt * 16 + l4;
#pragma unroll
        for (int nt = 0; nt < 4; nt++) {
            int c = cg * 32 + nt * 8 + c2;
            sF[r * SF_STR + c]       = acc[rt][nt][0] + sBias[c];
            sF[r * SF_STR + c + 1]   = acc[rt][nt][1] + sBias[c + 1];
            sF[(r + 8) * SF_STR + c]     = acc[rt][nt][2] + sBias[c];
            sF[(r + 8) * SF_STR + c + 1] = acc[rt][nt][3] + sBias[c + 1];
        }
    }
    if (tid < 128) {                 // softmax0, float4 row access
        float4* p4 = (float4*)&sScr[tid * 16];
        float4 a = p4[0], b = p4[1], c = p4[2], d = p4[3];
        float mx = fmaxf(fmaxf(fmaxf(a.x, a.y), fmaxf(a.z, a.w)),
                   fmaxf(fmaxf(fmaxf(b.x, b.y), fmaxf(b.z, b.w)),
                   fmaxf(fmaxf(fmaxf(c.x, c.y), fmaxf(c.z, c.w)),
                         fmaxf(fmaxf(d.x, d.y), fmaxf(d.z, d.w)))));
        a.x = expf(a.x - mx); a.y = expf(a.y - mx); a.z = expf(a.z - mx); a.w = expf(a.w - mx);
        b.x = expf(b.x - mx); b.y = expf(b.y - mx); b.z = expf(b.z - mx); b.w = expf(b.w - mx);
        c.x = expf(c.x - mx); c.y = expf(c.y - mx); c.z = expf(c.z - mx); c.w = expf(c.w - mx);
        d.x = expf(d.x - mx); d.y = expf(d.y - mx); d.z = expf(d.z - mx); d.w = expf(d.w - mx);
        float sum = a.x + a.y + a.z + a.w + b.x + b.y + b.z + b.w
                  + c.x + c.y + c.z + c.w + d.x + d.y + d.z + d.w;
        float inv = 1.f / sum;
        a.x *= inv; a.y *= inv; a.z *= inv; a.w *= inv;
        b.x *= inv; b.y *= inv; b.z *= inv; b.w *= inv;
        c.x *= inv; c.y *= inv; c.z *= inv; c.w *= inv;
        d.x *= inv; d.y *= inv; d.z *= inv; d.w *= inv;
        p4[0] = a; p4[1] = b; p4[2] = c; p4[3] = d;
    }
    __syncthreads();
    lw_issue(sm, sb, 2, tid);

    // O0 = Iq + A @ V0f -> sSm (32 rows)
#pragma unroll
    for (int it = 0; it < 2; it++) {
        int idx = tid + it * 512;
        int d = (idx & 31) * 4, row = idx >> 5;
        int qi = row & 3, e = row >> 2, h = d >> 5;
        float4 o = *(const float4*)&sIq[qi * 128 + d];
        const float* A = &sScr[((e * 4 + h) * 4 + qi) * 16];
        const float* vv = &sF[(e * 16) * SF_STR + d];
#pragma unroll
        for (int s = 0; s < 16; s++) {
            float4 v = *(const float4*)&vv[s * SF_STR];
            float a = A[s];
            o.x += a * v.x; o.y += a * v.y; o.z += a * v.z; o.w += a * v.w;
        }
        *(float4*)&sSm[row * SF_STR + d] = o;
    }
    cp_wait();
    __syncthreads();

    // ===== Q1 = X@Wq1 + bq1 -> sF =====
#pragma unroll
    for (int i = 0; i < 2; i++)
#pragma unroll
        for (int j = 0; j < 4; j++)
#pragma unroll
            for (int q = 0; q < 4; q++) acc[i][j][q] = 0.f;
    gemm128(xh, xl, wh, wl, wid, lane, acc);
#pragma unroll
    for (int rt = 0; rt < 2; rt++) {
        int r = rg * 32 + rt * 16 + l4;
#pragma unroll
        for (int nt = 0; nt < 4; nt++) {
            int c = cg * 32 + nt * 8 + c2;
            sF[r * SF_STR + c]       = acc[rt][nt][0] + sBias[2 * 128 + c];
            sF[r * SF_STR + c + 1]   = acc[rt][nt][1] + sBias[2 * 128 + c + 1];
            sF[(r + 8) * SF_STR + c]     = acc[rt][nt][2] + sBias[2 * 128 + c];
            sF[(r + 8) * SF_STR + c + 1] = acc[rt][nt][3] + sBias[2 * 128 + c + 1];
        }
    }
    __syncthreads();                 // X dead
    lw_issue(sm, sb, 3, tid);
    // O0 -> X image rows 0..31
#pragma unroll
    for (int it = 0; it < 2; it++) {
        int i = tid + it * 512;
        int r = i >> 5, c = (i & 31) * 4;
        img_st4(sm, r, c, *(const float4*)&sSm[r * SF_STR + c]);
    }
    cp_wait();
    __syncthreads();

    // ===== T0 = O0@Wo0 ; Hset -> image rows 0..31 =====
    acc32[0][0] = acc32[0][1] = acc32[0][2] = acc32[0][3] = 0.f;
    acc32[1][0] = acc32[1][1] = acc32[1][2] = acc32[1][3] = 0.f;
    gemm32(xh, xl, wh, wl, wid, lane, acc32);
    __syncthreads();
    lw_issue(sm, sb, 4, tid);
    {
        int rt = wid >> 3, cg8 = wid & 7;
        int r = rt * 16 + l4;
#pragma unroll
        for (int nt = 0; nt < 2; nt++) {
            int c = cg8 * 16 + nt * 8 + c2;
            float v0 = sSm[r * SF_STR + c]     + fmaxf(acc32[nt][0] + sBias[128 + c], 0.f);
            float v1 = sSm[r * SF_STR + c + 1] + fmaxf(acc32[nt][1] + sBias[128 + c + 1], 0.f);
            int i0 = imgoff(r, c);
            *(uint32_t*)(sm + OFF_XH + i0) = bf2bits(v0, v1);
            float h0 = __bfloat162float(__float2bfloat16(v0));
            float h1 = __bfloat162float(__float2bfloat16(v1));
            *(uint32_t*)(sm + OFF_XL + i0) = bf2bits(v0 - h0, v1 - h1);
            float w0 = sSm[(r + 8) * SF_STR + c]     + fmaxf(acc32[nt][2] + sBias[128 + c], 0.f);
            float w1 = sSm[(r + 8) * SF_STR + c + 1] + fmaxf(acc32[nt][3] + sBias[128 + c + 1], 0.f);
            int i1 = imgoff(r + 8, c);
            *(uint32_t*)(sm + OFF_XH + i1) = bf2bits(w0, w1);
            float g0 = __bfloat162float(__float2bfloat16(w0));
            float g1 = __bfloat162float(__float2bfloat16(w1));
            *(uint32_t*)(sm + OFF_XL + i1) = bf2bits(w0 - g0, w1 - g1);
        }
    }
    cp_wait();
    __syncthreads();

    // ===== K1 = Hset@Wk1 + bk1 -> sK1 =====
    acc32[0][0] = acc32[0][1] = acc32[0][2] = acc32[0][3] = 0.f;
    acc32[1][0] = acc32[1][1] = acc32[1][2] = acc32[1][3] = 0.f;
    gemm32(xh, xl, wh, wl, wid, lane, acc32);
    {
        int rt = wid >> 3, cg8 = wid & 7;
        int r = rt * 16 + l4;
#pragma unroll
        for (int nt = 0; nt < 2; nt++) {
            int c = cg8 * 16 + nt * 8 + c2;
            sK1[r * SF_STR + c]       = acc32[nt][0] + sBias[3 * 128 + c];
            sK1[r * SF_STR + c + 1]   = acc32[nt][1] + sBias[3 * 128 + c + 1];
            sK1[(r + 8) * SF_STR + c]     = acc32[nt][2] + sBias[3 * 128 + c];
            sK1[(r + 8) * SF_STR + c + 1] = acc32[nt][3] + sBias[3 * 128 + c + 1];
        }
    }
    __syncthreads();
    lw_issue(sm, sb, 5, tid);
    cp_wait();
    __syncthreads();

    // ===== V1 = Hset@Wv1 + bv1 -> sSm =====
    acc32[0][0] = acc32[0][1] = acc32[0][2] = acc32[0][3] = 0.f;
    acc32[1][0] = acc32[1][1] = acc32[1][2] = acc32[1][3] = 0.f;
    gemm32(xh, xl, wh, wl, wid, lane, acc32);
    {
        int rt = wid >> 3, cg8 = wid & 7;
        int r = rt * 16 + l4;
#pragma unroll
        for (int nt = 0; nt < 2; nt++) {
            int c = cg8 * 16 + nt * 8 + c2;
            sSm[r * SF_STR + c]       = acc32[nt][0] + sBias[4 * 128 + c];
            sSm[r * SF_STR + c + 1]   = acc32[nt][1] + sBias[4 * 128 + c + 1];
            sSm[(r + 8) * SF_STR + c]     = acc32[nt][2] + sBias[4 * 128 + c];
            sSm[(r + 8) * SF_STR + c + 1] = acc32[nt][3] + sBias[4 * 128 + c + 1];
        }
    }
    __syncthreads();
    lw_issue(sm, sb, 6, tid);

    // scores1
#pragma unroll
    for (int it = 0; it < 4; it++) {
        int idx = tid + it * 512;
        int k = idx & 3, q = (idx >> 2) & 15, h = (idx >> 6) & 3, e = idx >> 8;
        const float4* qv = (const float4*)&sF[(e * 16 + q) * SF_STR + h * 32];
        const float4* kv = (const float4*)&sK1[(e * 4 + k) * SF_STR + h * 32];
        float dot = 0.f;
#pragma unroll
        for (int d4 = 0; d4 < 8; d4++) {
            float4 qq = qv[d4], kk = kv[d4];
            dot += qq.x * kk.x + qq.y * kk.y + qq.z * kk.z + qq.w * kk.w;
        }
        sScr[idx] = dot * SCALE_INV;
    }
    __syncthreads();
    {   // softmax1
        float* p = &sScr[tid * 4];
        float mx = fmaxf(fmaxf(p[0], p[1]), fmaxf(p[2], p[3]));
        float e0 = expf(p[0] - mx), e1 = expf(p[1] - mx), e2 = expf(p[2] - mx), e3 = expf(p[3] - mx);
        float inv = 1.f / (e0 + e1 + e2 + e3);
        p[0] = e0 * inv; p[1] = e1 * inv; p[2] = e2 * inv; p[3] = e3 * inv;
    }
    __syncthreads();

    // O = Q1 + A1@V1f, fused sF update + X image write
#pragma unroll
    for (int it = 0; it < 8; it++) {
        int idx = tid + it * 512;
        int d = (idx & 31) * 4, row = idx >> 5;
        int q = row & 15, e = row >> 4, h = d >> 5;
        float4 o = *(const float4*)&sF[row * SF_STR + d];
        const float* A = &sScr[((e * 4 + h) * 16 + q) * 4];
#pragma unroll
        for (int k = 0; k < 4; k++) {
            float4 v = *(const float4*)&sSm[(e * 4 + k) * SF_STR + d];
            float a = A[k];
            o.x += a * v.x; o.y += a * v.y; o.z += a * v.z; o.w += a * v.w;
        }
        *(float4*)&sF[row * SF_STR + d] = o;
        img_st4(sm, row, d, o);
    }
    cp_wait();
    __syncthreads();

    // ===== T1 = O@Wo1 ; final -> sF in place =====
#pragma unroll
    for (int i = 0; i < 2; i++)
#pragma unroll
        for (int j = 0; j < 4; j++)
#pragma unroll
            for (int q = 0; q < 4; q++) acc[i][j][q] = 0.f;
    gemm128(xh, xl, wh, wl, wid, lane, acc);
#pragma unroll
    for (int rt = 0; rt < 2; rt++) {
        int r = rg * 32 + rt * 16 + l4;
#pragma unroll
        for (int nt = 0; nt < 4; nt++) {
            int c = cg * 32 + nt * 8 + c2;
            sF[r * SF_STR + c]       += fmaxf(acc[rt][nt][0] + sBias[5 * 128 + c], 0.f);
            sF[r * SF_STR + c + 1]   += fmaxf(acc[rt][nt][1] + sBias[5 * 128 + c + 1], 0.f);
            sF[(r + 8) * SF_STR + c]     += fmaxf(acc[rt][nt][2] + sBias[5 * 128 + c], 0.f);
            sF[(r + 8) * SF_STR + c + 1] += fmaxf(acc[rt][nt][3] + sBias[5 * 128 + c + 1], 0.f);
        }
    }
    __syncthreads();

    // logits
    if (tid < 256) {
        int r = tid >> 1, cb = (tid & 1) * 3;
        float a0 = sWo[768 + cb], a1 = sWo[768 + cb + 1], a2 = sWo[768 + cb + 2];
        const float4* xr = (const float4*)&sF[r * SF_STR];
#pragma unroll
        for (int k4 = 0; k4 < 32; k4++) {
            float4 x = xr[k4];
            const float* w0 = &sWo[(k4 * 4 + 0) * C_CLS + cb];
            const float* w1 = &sWo[(k4 * 4 + 1) * C_CLS + cb];
            const float* w2 = &sWo[(k4 * 4 + 2) * C_CLS + cb];
            const float* w3 = &sWo[(k4 * 4 + 3) * C_CLS + cb];
            a0 += x.x * w0[0] + x.y * w1[0] + x.z * w2[0] + x.w * w3[0];
            a1 += x.x * w0[1] + x.y * w1[1] + x.z * w2[1] + x.w * w3[1];
            a2 += x.x * w0[2] + x.y * w1[2] + x.z * w2[2] + x.w * w3[2];
        }
        long long off = (long long)(rowbase + r) * C_CLS + cb;
        if (off + 2 < out_capacity) {
            out[off] = a0; out[off + 1] = a1; out[off + 2] = a2;
        }
    }
    long long lab_base = (long long)E_EDGES * S_MEM * C_CLS;
    if (out_capacity >= lab_base + (long long)E_EDGES * S_MEM && tid < ROWS) {
        out[lab_base + rowbase + tid] = (float)labels[rowbase + tid];
    }
}

extern "C" void kernel_launch(void* const* d_in, const int* in_sizes, int n_in,
                              void* d_out, int out_size) {
    const float* Ws[8] = {0,0,0,0,0,0,0,0};
    const float* Bs[8] = {0,0,0,0,0,0,0,0};
    const float* vfeat = 0; const float* Iin = 0;
    const float* Wout = 0;  const float* bout = 0;
    const int* member_idx = 0; const int* labels = 0;
    int wi = 0, bi = 0, n_nodes = 500000;
    for (int i = 0; i < n_in; i++) {
        int sz = in_sizes[i];
        if (sz == 500000 * 128)      { vfeat = (const float*)d_in[i]; n_nodes = sz / D_DIM; }
        else if (sz == E_EDGES * S_MEM) {
            if (!member_idx) member_idx = (const int*)d_in[i];
            else if (!labels) labels = (const int*)d_in[i];
        }
        else if (sz == M_IND * D_DIM) Iin = (const float*)d_in[i];
        else if (sz == D_DIM * C_CLS) Wout = (const float*)d_in[i];
        else if (sz == C_CLS)         bout = (const float*)d_in[i];
        else if (sz == D_DIM * D_DIM) { if (wi < 8) Ws[wi++] = (const float*)d_in[i]; }
        else if (sz == D_DIM)         { if (bi < 8) Bs[bi++] = (const float*)d_in[i]; }
    }
    if (!vfeat || !member_idx || !labels || !Iin || !Wout || !bout || wi != 8 || bi != 8) {
        vfeat = (const float*)d_in[0]; member_idx = (const int*)d_in[1];
        labels = (const int*)d_in[2];  Iin = (const float*)d_in[3];
        Wout = (const float*)d_in[4];  bout = (const float*)d_in[5];
        for (int j = 0; j < 8; j++) { Ws[j] = (const float*)d_in[6 + 2 * j]; Bs[j] = (const float*)d_in[7 + 2 * j]; }
        n_nodes = in_sizes[0] / D_DIM;
    }
    const float *Wq0 = Ws[0], *Wk0 = Ws[1], *Wv0 = Ws[2], *Wo0 = Ws[3];
    const float *Wq1 = Ws[4], *Wk1 = Ws[5], *Wv1 = Ws[6], *Wo1 = Ws[7];
    const float *bq0 = Bs[0], *bk0 = Bs[1], *bv0 = Bs[2], *bo0 = Bs[3];
    const float *bq1 = Bs[4], *bk1 = Bs[5], *bv1 = Bs[6], *bo1 = Bs[7];

    cudaFuncSetAttribute(whatsnet_mma, cudaFuncAttributeMaxDynamicSharedMemorySize, SMEM_TOTAL);

    iq_kernel<<<2, 256>>>(Iin, Wq0, bq0);
    iqb_kernel<<<1, 32>>>(bk0);
    wconv_kernel<<<7, 256>>>(Wk0, Wv0, Wq1, Wo0, Wk1, Wv1, Wo1);

    whatsnet_mma<<<E_EDGES * S_MEM / ROWS, NTH, SMEM_TOTAL>>>(
        vfeat, member_idx, labels, Wout, bout,
        bv0, bo0, bq1, bk1, bv1, bo1,
        (float*)d_out, n_nodes, (long long)out_size);
}

// round 15
// speedup vs baseline: 1.5071x; 1.5071x over previous
#include <cuda_runtime.h>
#include <cuda_bf16.h>
#include <math.h>
#include <stdint.h>

#define E_EDGES 100000
#define S_MEM   16
#define D_DIM   128
#define C_CLS   6
#define M_IND   4
#define ROWS    128
#define NTH     512
#define SCALE_INV 0.08838834764831845f

// SMEM byte offsets
#define OFF_XH  0
#define OFF_XL  32768
#define OFF_WH  65536
#define OFF_WL  98304
#define OFF_SF  131072                 // f32 [128][132]
#define SF_STR  132
#define OFF_SSM (OFF_SF + 128*SF_STR*4)    // f32 [32][132]
#define OFF_BIAS (OFF_SSM + 32*SF_STR*4)   // f32 [6][128]
#define OFF_IQ  (OFF_BIAS + 6*128*4)       // f32 [512]
#define OFF_IQB (OFF_IQ + 2048)            // f32 [16]
#define OFF_WOUT (OFF_IQB + 64)            // f32 [776]
#define OFF_SCR (OFF_WOUT + 3104)          // f32 [2048]
#define SMEM_TOTAL (OFF_SCR + 8192)        // 232032 <= 232448

__device__ __align__(16) float g_Iq[M_IND * D_DIM];
__device__ __align__(16) float g_Iqb[16];
__device__ __align__(16) __nv_bfloat16 g_WH[7][16384];
__device__ __align__(16) __nv_bfloat16 g_WL[7][16384];

__host__ __device__ __forceinline__ int imgoff(int r, int c) {
    return r * 256 + (((c >> 3) ^ (r & 7)) << 4) + ((c & 7) << 1);
}

__device__ __forceinline__ uint32_t cvta_s(const void* p) {
    uint32_t a;
    asm("{ .reg .u64 t; cvta.to.shared.u64 t, %1; cvt.u32.u64 %0, t; }" : "=r"(a) : "l"(p));
    return a;
}
__device__ __forceinline__ void ldsm4(uint32_t* a, uint32_t addr) {
    asm volatile("ldmatrix.sync.aligned.m8n8.x4.shared.b16 {%0,%1,%2,%3}, [%4];"
        : "=r"(a[0]), "=r"(a[1]), "=r"(a[2]), "=r"(a[3]) : "r"(addr));
}
__device__ __forceinline__ void mma16816(float* c, const uint32_t* a, uint32_t b0, uint32_t b1) {
    asm volatile("mma.sync.aligned.m16n8k16.row.col.f32.bf16.bf16.f32 "
        "{%0,%1,%2,%3}, {%4,%5,%6,%7}, {%8,%9}, {%0,%1,%2,%3};"
        : "+f"(c[0]), "+f"(c[1]), "+f"(c[2]), "+f"(c[3])
        : "r"(a[0]), "r"(a[1]), "r"(a[2]), "r"(a[3]), "r"(b0), "r"(b1));
}
__device__ __forceinline__ void cp16(uint32_t dst, const void* src) {
    asm volatile("cp.async.cg.shared.global [%0], [%1], 16;" :: "r"(dst), "l"(src) : "memory");
}
__device__ __forceinline__ void cp_commit() { asm volatile("cp.async.commit_group;" ::: "memory"); }
__device__ __forceinline__ void cp_wait()   { asm volatile("cp.async.wait_group 0;" ::: "memory"); }

__device__ __forceinline__ uint32_t bf2bits(float a, float b) {
    __nv_bfloat162 p; p.x = __float2bfloat16(a); p.y = __float2bfloat16(b);
    return *(uint32_t*)&p;
}
__device__ __forceinline__ void img_st4(char* sm, int r, int c, float4 v) {
    int i = imgoff(r, c);
    float hx = __bfloat162float(__float2bfloat16(v.x));
    float hy = __bfloat162float(__float2bfloat16(v.y));
    float hz = __bfloat162float(__float2bfloat16(v.z));
    float hw = __bfloat162float(__float2bfloat16(v.w));
    uint2 hh, ll;
    hh.x = bf2bits(v.x, v.y);      hh.y = bf2bits(v.z, v.w);
    ll.x = bf2bits(v.x - hx, v.y - hy);
    ll.y = bf2bits(v.z - hz, v.w - hw);
    *(uint2*)(sm + OFF_XH + i) = hh;
    *(uint2*)(sm + OFF_XL + i) = ll;
}

// ---------------- prologs ----------------
__global__ void iq_kernel(const float* __restrict__ I, const float* __restrict__ Wq,
                          const float* __restrict__ bq) {
    int idx = blockIdx.x * blockDim.x + threadIdx.x;
    if (idx >= M_IND * D_DIM) return;
    int qi = idx / D_DIM, d = idx % D_DIM;
    float acc = bq[d];
    for (int k = 0; k < D_DIM; k++) acc += I[qi * D_DIM + k] * Wq[k * D_DIM + d];
    g_Iq[idx] = acc;
}
__global__ void iqb_kernel(const float* __restrict__ bk0) {
    int t = threadIdx.x;
    if (t < 16) {
        int qi = t >> 2, h = t & 3;
        float s = 0.f;
        for (int j = 0; j < 32; j++) s += g_Iq[qi * 128 + h * 32 + j] * bk0[h * 32 + j];
        g_Iqb[t] = s;
    }
}
__global__ void wconv_kernel(const float* W0, const float* W1, const float* W2, const float* W3,
                             const float* W4, const float* W5, const float* W6) {
    const float* W;
    int m = blockIdx.x;
    switch (m) { case 0: W = W0; break; case 1: W = W1; break; case 2: W = W2; break;
                 case 3: W = W3; break; case 4: W = W4; break; case 5: W = W5; break;
                 default: W = W6; }
    for (int i = threadIdx.x; i < 16384; i += blockDim.x) {
        int n = i >> 7, k = i & 127;
        float w = W[k * 128 + n];
        __nv_bfloat16 h = __float2bfloat16(w);
        int idx = n * 128 + (((k >> 3) ^ (n & 7)) << 3) + (k & 7);
        g_WH[m][idx] = h;
        g_WL[m][idx] = __float2bfloat16(w - __bfloat162float(h));
    }
}

__device__ __forceinline__ void lw_issue(char* sm, uint32_t sb, int widx, int tid) {
    const char* gh = (const char*)g_WH[widx];
    const char* gl = (const char*)g_WL[widx];
    uint32_t dh = sb + OFF_WH, dl = sb + OFF_WL;
#pragma unroll
    for (int i = 0; i < 4; i++) {
        int off = (tid + i * 512) * 16;
        cp16(dh + off, gh + off);
        cp16(dl + off, gl + off);
    }
    cp_commit();
}

// 128x128x128 GEMM, 16 warps: rowgroup wid>>1 (16 rows), colgroup wid&1 (64 cols)
// [round-13 mapping — do not change: 4x4 remap regressed 49% (round 14)]
__device__ __forceinline__ void gemm128(uint32_t xh, uint32_t xl, uint32_t wh, uint32_t wl,
                                        int wid, int lane, float acc[8][4]) {
    const int rg = wid >> 1, cg = wid & 1;
    const int lr = lane & 15, lh = lane >> 4;
    const int bn = (lane & 7) + ((lane >> 4) << 3);
    const int bh2 = (lane >> 3) & 1;
#pragma unroll
    for (int ks = 0; ks < 8; ks++) {
        uint32_t ah[4], al[4];
        int r = rg * 16 + lr;
        uint32_t off = (uint32_t)(r * 256 + (((ks * 2 + lh) ^ (r & 7)) << 4));
        ldsm4(ah, xh + off);
        ldsm4(al, xl + off);
#pragma unroll
        for (int ntp = 0; ntp < 4; ntp++) {
            int n = cg * 64 + ntp * 16 + bn;
            uint32_t boff = (uint32_t)(n * 256 + (((ks * 2 + bh2) ^ (n & 7)) << 4));
            uint32_t bh[4], bl[4];
            ldsm4(bh, wh + boff);
            ldsm4(bl, wl + boff);
            mma16816(acc[2 * ntp],     ah, bh[0], bh[1]);
            mma16816(acc[2 * ntp],     al, bh[0], bh[1]);
            mma16816(acc[2 * ntp],     ah, bl[0], bl[1]);
            mma16816(acc[2 * ntp + 1], ah, bh[2], bh[3]);
            mma16816(acc[2 * ntp + 1], al, bh[2], bh[3]);
            mma16816(acc[2 * ntp + 1], ah, bl[2], bl[3]);
        }
    }
}

// 32x128x128 GEMM, 16 warps: rowtile wid>>3 (16 rows), colgroup wid&7 (16 cols)
__device__ __forceinline__ void gemm32(uint32_t xh, uint32_t xl, uint32_t wh, uint32_t wl,
                                       int wid, int lane, float acc[2][4]) {
    const int rt = wid >> 3, cg8 = wid & 7;
    const int lr = lane & 15, lh = lane >> 4;
    const int bn = (lane & 7) + ((lane >> 4) << 3);
    const int bh2 = (lane >> 3) & 1;
#pragma unroll
    for (int ks = 0; ks < 8; ks++) {
        uint32_t ah[4], al[4];
        int r = rt * 16 + lr;
        uint32_t off = (uint32_t)(r * 256 + (((ks * 2 + lh) ^ (r & 7)) << 4));
        ldsm4(ah, xh + off);
        ldsm4(al, xl + off);
        int n = cg8 * 16 + bn;
        uint32_t boff = (uint32_t)(n * 256 + (((ks * 2 + bh2) ^ (n & 7)) << 4));
        uint32_t bh[4], bl[4];
        ldsm4(bh, wh + boff);
        ldsm4(bl, wl + boff);
        mma16816(acc[0], ah, bh[0], bh[1]);
        mma16816(acc[0], al, bh[0], bh[1]);
        mma16816(acc[0], ah, bl[0], bl[1]);
        mma16816(acc[1], ah, bh[2], bh[3]);
        mma16816(acc[1], al, bh[2], bh[3]);
        mma16816(acc[1], ah, bl[2], bl[3]);
    }
}

extern "C" __global__ void __launch_bounds__(NTH, 1)
whatsnet_mma(const float* __restrict__ vfeat, const int* __restrict__ member_idx,
             const int* __restrict__ labels,
             const float* __restrict__ Wout, const float* __restrict__ bout,
             const float* __restrict__ bv0, const float* __restrict__ bo0,
             const float* __restrict__ bq1, const float* __restrict__ bk1,
             const float* __restrict__ bv1, const float* __restrict__ bo1,
             float* __restrict__ out, int n_nodes, long long out_capacity)
{
    extern __shared__ char sm[];
    const int tid = threadIdx.x;
    const int wid = tid >> 5, lane = tid & 31;
    const int rowbase = blockIdx.x * ROWS;
    const uint32_t sb = cvta_s(sm);
    const uint32_t xh = sb + OFF_XH, xl = sb + OFF_XL;
    const uint32_t wh = sb + OFF_WH, wl = sb + OFF_WL;

    float* sF   = (float*)(sm + OFF_SF);
    float* sSm  = (float*)(sm + OFF_SSM);     // O0; later V1f
    float* sK1  = (float*)(sm + OFF_XH + 8704);  // K1f scratch, disjoint from image rows 0..31
    float* sBias= (float*)(sm + OFF_BIAS);
    float* sIq  = (float*)(sm + OFF_IQ);
    float* sIqb = (float*)(sm + OFF_IQB);
    float* sWo  = (float*)(sm + OFF_WOUT);
    float* sScr = (float*)(sm + OFF_SCR);

    // constants
    if (tid < 128) {
        sBias[0 * 128 + tid] = bv0[tid];
        sBias[1 * 128 + tid] = bo0[tid];
        sBias[2 * 128 + tid] = bq1[tid];
        sBias[3 * 128 + tid] = bk1[tid];
        sBias[4 * 128 + tid] = bv1[tid];
        sBias[5 * 128 + tid] = bo1[tid];
    }
    if (tid < 512) sIq[tid] = g_Iq[tid];
    if (tid < 16) sIqb[tid] = g_Iqb[tid];
    for (int i = tid; i < 768; i += NTH) sWo[i] = Wout[i];
    if (tid < 6) sWo[768 + tid] = bout[tid];

    lw_issue(sm, sb, 0, tid);

    // gather -> X images
    for (int r = wid; r < ROWS; r += 16) {
        int n = member_idx[rowbase + r];
        if (n < 0) n = 0;
        if (n >= n_nodes) n = n_nodes - 1;
        float4 v = *(const float4*)(vfeat + (size_t)n * D_DIM + lane * 4);
        img_st4(sm, r, lane * 4, v);
    }
    cp_wait();
    __syncthreads();

    const int l4 = lane >> 2, c2 = (lane & 3) * 2;
    const int rg = wid >> 1, cg = wid & 1;

    float acc[8][4];
    float acc32[2][4];

    // ===== K0 = X@Wk0 -> sF =====
#pragma unroll
    for (int j = 0; j < 8; j++)
#pragma unroll
        for (int q = 0; q < 4; q++) acc[j][q] = 0.f;
    gemm128(xh, xl, wh, wl, wid, lane, acc);
    {
        int r = rg * 16 + l4;
#pragma unroll
        for (int nt = 0; nt < 8; nt++) {
            int c = cg * 64 + nt * 8 + c2;
            sF[r * SF_STR + c]       = acc[nt][0];
            sF[r * SF_STR + c + 1]   = acc[nt][1];
            sF[(r + 8) * SF_STR + c]     = acc[nt][2];
            sF[(r + 8) * SF_STR + c + 1] = acc[nt][3];
        }
    }
    __syncthreads();
    lw_issue(sm, sb, 1, tid);

    // scores0
#pragma unroll
    for (int it = 0; it < 4; it++) {
        int idx = tid + it * 512;
        int s = idx & 15, qi = (idx >> 4) & 3, h = (idx >> 6) & 3, e = idx >> 8;
        const float4* qv = (const float4*)&sIq[qi * 128 + h * 32];
        const float4* kv = (const float4*)&sF[(e * 16 + s) * SF_STR + h * 32];
        float dot = sIqb[qi * 4 + h];
#pragma unroll
        for (int d4 = 0; d4 < 8; d4++) {
            float4 q = qv[d4], k = kv[d4];
            dot += q.x * k.x + q.y * k.y + q.z * k.z + q.w * k.w;
        }
        sScr[idx] = dot * SCALE_INV;
    }
    cp_wait();
    __syncthreads();

    // ===== V0 = X@Wv0 + bv0 -> sF ; softmax0 =====
#pragma unroll
    for (int j = 0; j < 8; j++)
#pragma unroll
        for (int q = 0; q < 4; q++) acc[j][q] = 0.f;
    gemm128(xh, xl, wh, wl, wid, lane, acc);
    {
        int r = rg * 16 + l4;
#pragma unroll
        for (int nt = 0; nt < 8; nt++) {
            int c = cg * 64 + nt * 8 + c2;
            sF[r * SF_STR + c]       = acc[nt][0] + sBias[c];
            sF[r * SF_STR + c + 1]   = acc[nt][1] + sBias[c + 1];
            sF[(r + 8) * SF_STR + c]     = acc[nt][2] + sBias[c];
            sF[(r + 8) * SF_STR + c + 1] = acc[nt][3] + sBias[c + 1];
        }
    }
    if (tid < 128) {                 // softmax0, float4 row access
        float4* p4 = (float4*)&sScr[tid * 16];
        float4 a = p4[0], b = p4[1], c = p4[2], d = p4[3];
        float mx = fmaxf(fmaxf(fmaxf(a.x, a.y), fmaxf(a.z, a.w)),
                   fmaxf(fmaxf(fmaxf(b.x, b.y), fmaxf(b.z, b.w)),
                   fmaxf(fmaxf(fmaxf(c.x, c.y), fmaxf(c.z, c.w)),
                         fmaxf(fmaxf(d.x, d.y), fmaxf(d.z, d.w)))));
        a.x = expf(a.x - mx); a.y = expf(a.y - mx); a.z = expf(a.z - mx); a.w = expf(a.w - mx);
        b.x = expf(b.x - mx); b.y = expf(b.y - mx); b.z = expf(b.z - mx); b.w = expf(b.w - mx);
        c.x = expf(c.x - mx); c.y = expf(c.y - mx); c.z = expf(c.z - mx); c.w = expf(c.w - mx);
        d.x = expf(d.x - mx); d.y = expf(d.y - mx); d.z = expf(d.z - mx); d.w = expf(d.w - mx);
        float sum = a.x + a.y + a.z + a.w + b.x + b.y + b.z + b.w
                  + c.x + c.y + c.z + c.w + d.x + d.y + d.z + d.w;
        float inv = 1.f / sum;
        a.x *= inv; a.y *= inv; a.z *= inv; a.w *= inv;
        b.x *= inv; b.y *= inv; b.z *= inv; b.w *= inv;
        c.x *= inv; c.y *= inv; c.z *= inv; c.w *= inv;
        d.x *= inv; d.y *= inv; d.z *= inv; d.w *= inv;
        p4[0] = a; p4[1] = b; p4[2] = c; p4[3] = d;
    }
    __syncthreads();
    lw_issue(sm, sb, 2, tid);

    // O0 = Iq + A @ V0f -> sSm (32 rows)
#pragma unroll
    for (int it = 0; it < 2; it++) {
        int idx = tid + it * 512;
        int d = (idx & 31) * 4, row = idx >> 5;
        int qi = row & 3, e = row >> 2, h = d >> 5;
        float4 o = *(const float4*)&sIq[qi * 128 + d];
        const float* A = &sScr[((e * 4 + h) * 4 + qi) * 16];
        const float* vv = &sF[(e * 16) * SF_STR + d];
#pragma unroll
        for (int s = 0; s < 16; s++) {
            float4 v = *(const float4*)&vv[s * SF_STR];
            float a = A[s];
            o.x += a * v.x; o.y += a * v.y; o.z += a * v.z; o.w += a * v.w;
        }
        *(float4*)&sSm[row * SF_STR + d] = o;
    }
    cp_wait();
    __syncthreads();

    // ===== Q1 = X@Wq1 + bq1 -> sF =====
#pragma unroll
    for (int j = 0; j < 8; j++)
#pragma unroll
        for (int q = 0; q < 4; q++) acc[j][q] = 0.f;
    gemm128(xh, xl, wh, wl, wid, lane, acc);
    {
        int r = rg * 16 + l4;
#pragma unroll
        for (int nt = 0; nt < 8; nt++) {
            int c = cg * 64 + nt * 8 + c2;
            sF[r * SF_STR + c]       = acc[nt][0] + sBias[2 * 128 + c];
            sF[r * SF_STR + c + 1]   = acc[nt][1] + sBias[2 * 128 + c + 1];
            sF[(r + 8) * SF_STR + c]     = acc[nt][2] + sBias[2 * 128 + c];
            sF[(r + 8) * SF_STR + c + 1] = acc[nt][3] + sBias[2 * 128 + c + 1];
        }
    }
    __syncthreads();                 // X dead
    lw_issue(sm, sb, 3, tid);
    // O0 -> X image rows 0..31
#pragma unroll
    for (int it = 0; it < 2; it++) {
        int i = tid + it * 512;
        int r = i >> 5, c = (i & 31) * 4;
        img_st4(sm, r, c, *(const float4*)&sSm[r * SF_STR + c]);
    }
    cp_wait();
    __syncthreads();

    // ===== T0 = O0@Wo0 ; Hset -> image rows 0..31 =====
    acc32[0][0] = acc32[0][1] = acc32[0][2] = acc32[0][3] = 0.f;
    acc32[1][0] = acc32[1][1] = acc32[1][2] = acc32[1][3] = 0.f;
    gemm32(xh, xl, wh, wl, wid, lane, acc32);
    __syncthreads();
    lw_issue(sm, sb, 4, tid);
    {
        int rt = wid >> 3, cg8 = wid & 7;
        int r = rt * 16 + l4;
#pragma unroll
        for (int nt = 0; nt < 2; nt++) {
            int c = cg8 * 16 + nt * 8 + c2;
            float v0 = sSm[r * SF_STR + c]     + fmaxf(acc32[nt][0] + sBias[128 + c], 0.f);
            float v1 = sSm[r * SF_STR + c + 1] + fmaxf(acc32[nt][1] + sBias[128 + c + 1], 0.f);
            int i0 = imgoff(r, c);
            *(uint32_t*)(sm + OFF_XH + i0) = bf2bits(v0, v1);
            float h0 = __bfloat162float(__float2bfloat16(v0));
            float h1 = __bfloat162float(__float2bfloat16(v1));
            *(uint32_t*)(sm + OFF_XL + i0) = bf2bits(v0 - h0, v1 - h1);
            float w0 = sSm[(r + 8) * SF_STR + c]     + fmaxf(acc32[nt][2] + sBias[128 + c], 0.f);
            float w1 = sSm[(r + 8) * SF_STR + c + 1] + fmaxf(acc32[nt][3] + sBias[128 + c + 1], 0.f);
            int i1 = imgoff(r + 8, c);
            *(uint32_t*)(sm + OFF_XH + i1) = bf2bits(w0, w1);
            float g0 = __bfloat162float(__float2bfloat16(w0));
            float g1 = __bfloat162float(__float2bfloat16(w1));
            *(uint32_t*)(sm + OFF_XL + i1) = bf2bits(w0 - g0, w1 - g1);
        }
    }
    cp_wait();
    __syncthreads();                 // Hset image + W4 visible

    // ===== K1 = Hset@Wk1 + bk1 -> sK1 =====
    acc32[0][0] = acc32[0][1] = acc32[0][2] = acc32[0][3] = 0.f;
    acc32[1][0] = acc32[1][1] = acc32[1][2] = acc32[1][3] = 0.f;
    gemm32(xh, xl, wh, wl, wid, lane, acc32);
    {
        int rt = wid >> 3, cg8 = wid & 7;
        int r = rt * 16 + l4;
#pragma unroll
        for (int nt = 0; nt < 2; nt++) {
            int c = cg8 * 16 + nt * 8 + c2;
            sK1[r * SF_STR + c]       = acc32[nt][0] + sBias[3 * 128 + c];
            sK1[r * SF_STR + c + 1]   = acc32[nt][1] + sBias[3 * 128 + c + 1];
            sK1[(r + 8) * SF_STR + c]     = acc32[nt][2] + sBias[3 * 128 + c];
            sK1[(r + 8) * SF_STR + c + 1] = acc32[nt][3] + sBias[3 * 128 + c + 1];
        }
    }
    __syncthreads();                 // W4 reads done; sK1 visible
    lw_issue(sm, sb, 5, tid);        // stage Wv1 — overlapped by scores1 below

    // scores1 (reads sF=Q1, sK1; overlaps W5 staging)
#pragma unroll
    for (int it = 0; it < 4; it++) {
        int idx = tid + it * 512;
        int k = idx & 3, q = (idx >> 2) & 15, h = (idx >> 6) & 3, e = idx >> 8;
        const float4* qv = (const float4*)&sF[(e * 16 + q) * SF_STR + h * 32];
        const float4* kv = (const float4*)&sK1[(e * 4 + k) * SF_STR + h * 32];
        float dot = 0.f;
#pragma unroll
        for (int d4 = 0; d4 < 8; d4++) {
            float4 qq = qv[d4], kk = kv[d4];
            dot += qq.x * kk.x + qq.y * kk.y + qq.z * kk.z + qq.w * kk.w;
        }
        sScr[idx] = dot * SCALE_INV;
    }
    cp_wait();
    __syncthreads();                 // scores1 + W5 visible

    // ===== V1 = Hset@Wv1 + bv1 -> sSm ; softmax1 in same phase =====
    acc32[0][0] = acc32[0][1] = acc32[0][2] = acc32[0][3] = 0.f;
    acc32[1][0] = acc32[1][1] = acc32[1][2] = acc32[1][3] = 0.f;
    gemm32(xh, xl, wh, wl, wid, lane, acc32);
    {
        int rt = wid >> 3, cg8 = wid & 7;
        int r = rt * 16 + l4;
#pragma unroll
        for (int nt = 0; nt < 2; nt++) {
            int c = cg8 * 16 + nt * 8 + c2;
            sSm[r * SF_STR + c]       = acc32[nt][0] + sBias[4 * 128 + c];
            sSm[r * SF_STR + c + 1]   = acc32[nt][1] + sBias[4 * 128 + c + 1];
            sSm[(r + 8) * SF_STR + c]     = acc32[nt][2] + sBias[4 * 128 + c];
            sSm[(r + 8) * SF_STR + c + 1] = acc32[nt][3] + sBias[4 * 128 + c + 1];
        }
    }
    {   // softmax1: 512 rows, one per thread (touches only sScr — disjoint)
        float* p = &sScr[tid * 4];
        float mx = fmaxf(fmaxf(p[0], p[1]), fmaxf(p[2], p[3]));
        float e0 = expf(p[0] - mx), e1 = expf(p[1] - mx), e2 = expf(p[2] - mx), e3 = expf(p[3] - mx);
        float inv = 1.f / (e0 + e1 + e2 + e3);
        p[0] = e0 * inv; p[1] = e1 * inv; p[2] = e2 * inv; p[3] = e3 * inv;
    }
    __syncthreads();                 // V1f + softmax1 visible; W5 reads done
    lw_issue(sm, sb, 6, tid);        // stage Wo1 — overlapped by O-update below

    // O = Q1 + A1@V1f, fused sF update + X image write (K1f dead; image rows all)
#pragma unroll
    for (int it = 0; it < 8; it++) {
        int idx = tid + it * 512;
        int d = (idx & 31) * 4, row = idx >> 5;
        int q = row & 15, e = row >> 4, h = d >> 5;
        float4 o = *(const float4*)&sF[row * SF_STR + d];
        const float* A = &sScr[((e * 4 + h) * 16 + q) * 4];
#pragma unroll
        for (int k = 0; k < 4; k++) {
            float4 v = *(const float4*)&sSm[(e * 4 + k) * SF_STR + d];
            float a = A[k];
            o.x += a * v.x; o.y += a * v.y; o.z += a * v.z; o.w += a * v.w;
        }
        *(float4*)&sF[row * SF_STR + d] = o;
        img_st4(sm, row, d, o);
    }
    cp_wait();
    __syncthreads();                 // O image + W6 visible

    // ===== T1 = O@Wo1 ; final -> sF in place =====
#pragma unroll
    for (int j = 0; j < 8; j++)
#pragma unroll
        for (int q = 0; q < 4; q++) acc[j][q] = 0.f;
    gemm128(xh, xl, wh, wl, wid, lane, acc);
    {
        int r = rg * 16 + l4;
#pragma unroll
        for (int nt = 0; nt < 8; nt++) {
            int c = cg * 64 + nt * 8 + c2;
            sF[r * SF_STR + c]       += fmaxf(acc[nt][0] + sBias[5 * 128 + c], 0.f);
            sF[r * SF_STR + c + 1]   += fmaxf(acc[nt][1] + sBias[5 * 128 + c + 1], 0.f);
            sF[(r + 8) * SF_STR + c]     += fmaxf(acc[nt][2] + sBias[5 * 128 + c], 0.f);
            sF[(r + 8) * SF_STR + c + 1] += fmaxf(acc[nt][3] + sBias[5 * 128 + c + 1], 0.f);
        }
    }
    __syncthreads();

    // logits: first 256 threads, 2 per row x 3 cols
    if (tid < 256) {
        int r = tid >> 1, cb = (tid & 1) * 3;
        float a0 = sWo[768 + cb], a1 = sWo[768 + cb + 1], a2 = sWo[768 + cb + 2];
        const float4* xr = (const float4*)&sF[r * SF_STR];
#pragma unroll
        for (int k4 = 0; k4 < 32; k4++) {
            float4 x = xr[k4];
            const float* w0 = &sWo[(k4 * 4 + 0) * C_CLS + cb];
            const float* w1 = &sWo[(k4 * 4 + 1) * C_CLS + cb];
            const float* w2 = &sWo[(k4 * 4 + 2) * C_CLS + cb];
            const float* w3 = &sWo[(k4 * 4 + 3) * C_CLS + cb];
            a0 += x.x * w0[0] + x.y * w1[0] + x.z * w2[0] + x.w * w3[0];
            a1 += x.x * w0[1] + x.y * w1[1] + x.z * w2[1] + x.w * w3[1];
            a2 += x.x * w0[2] + x.y * w1[2] + x.z * w2[2] + x.w * w3[2];
        }
        long long off = (long long)(rowbase + r) * C_CLS + cb;
        if (off + 2 < out_capacity) {
            out[off] = a0; out[off + 1] = a1; out[off + 2] = a2;
        }
    }
    long long lab_base = (long long)E_EDGES * S_MEM * C_CLS;
    if (out_capacity >= lab_base + (long long)E_EDGES * S_MEM && tid < ROWS) {
        out[lab_base + rowbase + tid] = (float)labels[rowbase + tid];
    }
}

extern "C" void kernel_launch(void* const* d_in, const int* in_sizes, int n_in,
                              void* d_out, int out_size) {
    const float* Ws[8] = {0,0,0,0,0,0,0,0};
    const float* Bs[8] = {0,0,0,0,0,0,0,0};
    const float* vfeat = 0; const float* Iin = 0;
    const float* Wout = 0;  const float* bout = 0;
    const int* member_idx = 0; const int* labels = 0;
    int wi = 0, bi = 0, n_nodes = 500000;
    for (int i = 0; i < n_in; i++) {
        int sz = in_sizes[i];
        if (sz == 500000 * 128)      { vfeat = (const float*)d_in[i]; n_nodes = sz / D_DIM; }
        else if (sz == E_EDGES * S_MEM) {
            if (!member_idx) member_idx = (const int*)d_in[i];
            else if (!labels) labels = (const int*)d_in[i];
        }
        else if (sz == M_IND * D_DIM) Iin = (const float*)d_in[i];
        else if (sz == D_DIM * C_CLS) Wout = (const float*)d_in[i];
        else if (sz == C_CLS)         bout = (const float*)d_in[i];
        else if (sz == D_DIM * D_DIM) { if (wi < 8) Ws[wi++] = (const float*)d_in[i]; }
        else if (sz == D_DIM)         { if (bi < 8) Bs[bi++] = (const float*)d_in[i]; }
    }
    if (!vfeat || !member_idx || !labels || !Iin || !Wout || !bout || wi != 8 || bi != 8) {
        vfeat = (const float*)d_in[0]; member_idx = (const int*)d_in[1];
        labels = (const int*)d_in[2];  Iin = (const float*)d_in[3];
        Wout = (const float*)d_in[4];  bout = (const float*)d_in[5];
        for (int j = 0; j < 8; j++) { Ws[j] = (const float*)d_in[6 + 2 * j]; Bs[j] = (const float*)d_in[7 + 2 * j]; }
        n_nodes = in_sizes[0] / D_DIM;
    }
    const float *Wq0 = Ws[0], *Wk0 = Ws[1], *Wv0 = Ws[2], *Wo0 = Ws[3];
    const float *Wq1 = Ws[4], *Wk1 = Ws[5], *Wv1 = Ws[6], *Wo1 = Ws[7];
    const float *bq0 = Bs[0], *bk0 = Bs[1], *bv0 = Bs[2], *bo0 = Bs[3];
    const float *bq1 = Bs[4], *bk1 = Bs[5], *bv1 = Bs[6], *bo1 = Bs[7];

    cudaFuncSetAttribute(whatsnet_mma, cudaFuncAttributeMaxDynamicSharedMemorySize, SMEM_TOTAL);

    iq_kernel<<<2, 256>>>(Iin, Wq0, bq0);
    iqb_kernel<<<1, 32>>>(bk0);
    wconv_kernel<<<7, 256>>>(Wk0, Wv0, Wq1, Wo0, Wk1, Wv1, Wo1);

    whatsnet_mma<<<E_EDGES * S_MEM / ROWS, NTH, SMEM_TOTAL>>>(
        vfeat, member_idx, labels, Wout, bout,
        bv0, bo0, bq1, bk1, bv1, bo1,
        (float*)d_out, n_nodes, (long long)out_size);
}

// round 16
// speedup vs baseline: 1.6250x; 1.0783x over previous
#include <cuda_runtime.h>
#include <cuda_bf16.h>
#include <math.h>
#include <stdint.h>

#define E_EDGES 100000
#define S_MEM   16
#define D_DIM   128
#define C_CLS   6
#define M_IND   4
#define ROWS    128
#define NTH     512
#define SCALE_INV 0.08838834764831845f

// SMEM byte offsets
#define OFF_XH  0
#define OFF_XL  32768
#define OFF_WH  65536
#define OFF_WL  98304
#define OFF_SF  131072                 // f32 [128][132]
#define SF_STR  132
#define OFF_SSM (OFF_SF + 128*SF_STR*4)    // f32 [32][132]
#define OFF_BIAS (OFF_SSM + 32*SF_STR*4)   // f32 [6][128]
#define OFF_IQ  (OFF_BIAS + 6*128*4)       // f32 [512]
#define OFF_IQB (OFF_IQ + 2048)            // f32 [16]
#define OFF_WOUT (OFF_IQB + 64)            // f32 [776]
#define OFF_SCR (OFF_WOUT + 3104)          // f32 [2048]
#define SMEM_TOTAL (OFF_SCR + 8192)        // 232032 <= 232448

__device__ __align__(16) float g_Iq[M_IND * D_DIM];
__device__ __align__(16) float g_Iqb[16];
__device__ __align__(16) __nv_bfloat16 g_WH[7][16384];
__device__ __align__(16) __nv_bfloat16 g_WL[7][16384];
// folded scores weight P[n][k], n = h*4+qi (16 rows), frag layout like g_WH rows
__device__ __align__(16) __nv_bfloat16 g_PH[2048];
__device__ __align__(16) __nv_bfloat16 g_PL[2048];

__host__ __device__ __forceinline__ int imgoff(int r, int c) {
    return r * 256 + (((c >> 3) ^ (r & 7)) << 4) + ((c & 7) << 1);
}

__device__ __forceinline__ uint32_t cvta_s(const void* p) {
    uint32_t a;
    asm("{ .reg .u64 t; cvta.to.shared.u64 t, %1; cvt.u32.u64 %0, t; }" : "=r"(a) : "l"(p));
    return a;
}
__device__ __forceinline__ void ldsm4(uint32_t* a, uint32_t addr) {
    asm volatile("ldmatrix.sync.aligned.m8n8.x4.shared.b16 {%0,%1,%2,%3}, [%4];"
        : "=r"(a[0]), "=r"(a[1]), "=r"(a[2]), "=r"(a[3]) : "r"(addr));
}
__device__ __forceinline__ void mma16816(float* c, const uint32_t* a, uint32_t b0, uint32_t b1) {
    asm volatile("mma.sync.aligned.m16n8k16.row.col.f32.bf16.bf16.f32 "
        "{%0,%1,%2,%3}, {%4,%5,%6,%7}, {%8,%9}, {%0,%1,%2,%3};"
        : "+f"(c[0]), "+f"(c[1]), "+f"(c[2]), "+f"(c[3])
        : "r"(a[0]), "r"(a[1]), "r"(a[2]), "r"(a[3]), "r"(b0), "r"(b1));
}
__device__ __forceinline__ void cp16(uint32_t dst, const void* src) {
    asm volatile("cp.async.cg.shared.global [%0], [%1], 16;" :: "r"(dst), "l"(src) : "memory");
}
__device__ __forceinline__ void cp_commit() { asm volatile("cp.async.commit_group;" ::: "memory"); }
__device__ __forceinline__ void cp_wait()   { asm volatile("cp.async.wait_group 0;" ::: "memory"); }

__device__ __forceinline__ uint32_t bf2bits(float a, float b) {
    __nv_bfloat162 p; p.x = __float2bfloat16(a); p.y = __float2bfloat16(b);
    return *(uint32_t*)&p;
}
__device__ __forceinline__ void img_st4(char* sm, int r, int c, float4 v) {
    int i = imgoff(r, c);
    float hx = __bfloat162float(__float2bfloat16(v.x));
    float hy = __bfloat162float(__float2bfloat16(v.y));
    float hz = __bfloat162float(__float2bfloat16(v.z));
    float hw = __bfloat162float(__float2bfloat16(v.w));
    uint2 hh, ll;
    hh.x = bf2bits(v.x, v.y);      hh.y = bf2bits(v.z, v.w);
    ll.x = bf2bits(v.x - hx, v.y - hy);
    ll.y = bf2bits(v.z - hz, v.w - hw);
    *(uint2*)(sm + OFF_XH + i) = hh;
    *(uint2*)(sm + OFF_XL + i) = ll;
}

// ---------------- prologs ----------------
__global__ void iq_kernel(const float* __restrict__ I, const float* __restrict__ Wq,
                          const float* __restrict__ bq) {
    int idx = blockIdx.x * blockDim.x + threadIdx.x;
    if (idx >= M_IND * D_DIM) return;
    int qi = idx / D_DIM, d = idx % D_DIM;
    float acc = bq[d];
    for (int k = 0; k < D_DIM; k++) acc += I[qi * D_DIM + k] * Wq[k * D_DIM + d];
    g_Iq[idx] = acc;
}
__global__ void iqb_kernel(const float* __restrict__ bk0) {
    int t = threadIdx.x;
    if (t < 16) {
        int qi = t >> 2, h = t & 3;
        float s = 0.f;
        for (int j = 0; j < 32; j++) s += g_Iq[qi * 128 + h * 32 + j] * bk0[h * 32 + j];
        g_Iqb[t] = s;
    }
}
// P[n=h*4+qi][k] = sum_{j<32} Wk0[k][h*32+j] * Iq[qi][h*32+j]; frag-image layout
__global__ void p_kernel(const float* __restrict__ Wk0) {
    int t = blockIdx.x * blockDim.x + threadIdx.x;
    if (t >= 2048) return;
    int n = t >> 7, k = t & 127;
    int h = n >> 2, qi = n & 3;
    float p = 0.f;
    for (int j = 0; j < 32; j++) p += Wk0[k * 128 + h * 32 + j] * g_Iq[qi * 128 + h * 32 + j];
    __nv_bfloat16 hh = __float2bfloat16(p);
    int idx = n * 128 + (((k >> 3) ^ (n & 7)) << 3) + (k & 7);
    g_PH[idx] = hh;
    g_PL[idx] = __float2bfloat16(p - __bfloat162float(hh));
}
__global__ void wconv_kernel(const float* W0, const float* W1, const float* W2, const float* W3,
                             const float* W4, const float* W5, const float* W6) {
    const float* W;
    int m = blockIdx.x;
    switch (m) { case 0: W = W0; break; case 1: W = W1; break; case 2: W = W2; break;
                 case 3: W = W3; break; case 4: W = W4; break; case 5: W = W5; break;
                 default: W = W6; }
    for (int i = threadIdx.x; i < 16384; i += blockDim.x) {
        int n = i >> 7, k = i & 127;
        float w = W[k * 128 + n];
        __nv_bfloat16 h = __float2bfloat16(w);
        int idx = n * 128 + (((k >> 3) ^ (n & 7)) << 3) + (k & 7);
        g_WH[m][idx] = h;
        g_WL[m][idx] = __float2bfloat16(w - __bfloat162float(h));
    }
}

__device__ __forceinline__ void lw_issue(char* sm, uint32_t sb, int widx, int tid) {
    const char* gh = (const char*)g_WH[widx];
    const char* gl = (const char*)g_WL[widx];
    uint32_t dh = sb + OFF_WH, dl = sb + OFF_WL;
#pragma unroll
    for (int i = 0; i < 4; i++) {
        int off = (tid + i * 512) * 16;
        cp16(dh + off, gh + off);
        cp16(dl + off, gl + off);
    }
    cp_commit();
}
__device__ __forceinline__ void lw_issueP(char* sm, uint32_t sb, int tid) {
    if (tid < 256) cp16(sb + OFF_WH + tid * 16, (const char*)g_PH + tid * 16);
    else if (tid < 512) cp16(sb + OFF_WL + (tid - 256) * 16, (const char*)g_PL + (tid - 256) * 16);
    cp_commit();
}

// 128x128x128 GEMM, 16 warps: rowgroup wid>>1 (16 rows), colgroup wid&1 (64 cols)
// [round-13 mapping — 4x4 remap regressed 49% (round 14); do not change]
__device__ __forceinline__ void gemm128(uint32_t xh, uint32_t xl, uint32_t wh, uint32_t wl,
                                        int wid, int lane, float acc[8][4]) {
    const int rg = wid >> 1, cg = wid & 1;
    const int lr = lane & 15, lh = lane >> 4;
    const int bn = (lane & 7) + ((lane >> 4) << 3);
    const int bh2 = (lane >> 3) & 1;
#pragma unroll
    for (int ks = 0; ks < 8; ks++) {
        uint32_t ah[4], al[4];
        int r = rg * 16 + lr;
        uint32_t off = (uint32_t)(r * 256 + (((ks * 2 + lh) ^ (r & 7)) << 4));
        ldsm4(ah, xh + off);
        ldsm4(al, xl + off);
#pragma unroll
        for (int ntp = 0; ntp < 4; ntp++) {
            int n = cg * 64 + ntp * 16 + bn;
            uint32_t boff = (uint32_t)(n * 256 + (((ks * 2 + bh2) ^ (n & 7)) << 4));
            uint32_t bh[4], bl[4];
            ldsm4(bh, wh + boff);
            ldsm4(bl, wl + boff);
            mma16816(acc[2 * ntp],     ah, bh[0], bh[1]);
            mma16816(acc[2 * ntp],     al, bh[0], bh[1]);
            mma16816(acc[2 * ntp],     ah, bl[0], bl[1]);
            mma16816(acc[2 * ntp + 1], ah, bh[2], bh[3]);
            mma16816(acc[2 * ntp + 1], al, bh[2], bh[3]);
            mma16816(acc[2 * ntp + 1], ah, bl[2], bl[3]);
        }
    }
}

// 32x128x128 GEMM, 16 warps
__device__ __forceinline__ void gemm32(uint32_t xh, uint32_t xl, uint32_t wh, uint32_t wl,
                                       int wid, int lane, float acc[2][4]) {
    const int rt = wid >> 3, cg8 = wid & 7;
    const int lr = lane & 15, lh = lane >> 4;
    const int bn = (lane & 7) + ((lane >> 4) << 3);
    const int bh2 = (lane >> 3) & 1;
#pragma unroll
    for (int ks = 0; ks < 8; ks++) {
        uint32_t ah[4], al[4];
        int r = rt * 16 + lr;
        uint32_t off = (uint32_t)(r * 256 + (((ks * 2 + lh) ^ (r & 7)) << 4));
        ldsm4(ah, xh + off);
        ldsm4(al, xl + off);
        int n = cg8 * 16 + bn;
        uint32_t boff = (uint32_t)(n * 256 + (((ks * 2 + bh2) ^ (n & 7)) << 4));
        uint32_t bh[4], bl[4];
        ldsm4(bh, wh + boff);
        ldsm4(bl, wl + boff);
        mma16816(acc[0], ah, bh[0], bh[1]);
        mma16816(acc[0], al, bh[0], bh[1]);
        mma16816(acc[0], ah, bl[0], bl[1]);
        mma16816(acc[1], ah, bh[2], bh[3]);
        mma16816(acc[1], al, bh[2], bh[3]);
        mma16816(acc[1], ah, bl[2], bl[3]);
    }
}

extern "C" __global__ void __launch_bounds__(NTH, 1)
whatsnet_mma(const float* __restrict__ vfeat, const int* __restrict__ member_idx,
             const int* __restrict__ labels,
             const float* __restrict__ Wout, const float* __restrict__ bout,
             const float* __restrict__ bv0, const float* __restrict__ bo0,
             const float* __restrict__ bq1, const float* __restrict__ bk1,
             const float* __restrict__ bv1, const float* __restrict__ bo1,
             float* __restrict__ out, int n_nodes, long long out_capacity)
{
    extern __shared__ char sm[];
    const int tid = threadIdx.x;
    const int wid = tid >> 5, lane = tid & 31;
    const int rowbase = blockIdx.x * ROWS;
    const uint32_t sb = cvta_s(sm);
    const uint32_t xh = sb + OFF_XH, xl = sb + OFF_XL;
    const uint32_t wh = sb + OFF_WH, wl = sb + OFF_WL;

    float* sF   = (float*)(sm + OFF_SF);
    float* sSm  = (float*)(sm + OFF_SSM);     // O0; later V1f
    float* sK1  = (float*)(sm + OFF_XH + 8704);
    float* sBias= (float*)(sm + OFF_BIAS);
    float* sIq  = (float*)(sm + OFF_IQ);
    float* sIqb = (float*)(sm + OFF_IQB);
    float* sWo  = (float*)(sm + OFF_WOUT);
    float* sScr = (float*)(sm + OFF_SCR);

    // constants
    if (tid < 128) {
        sBias[0 * 128 + tid] = bv0[tid];
        sBias[1 * 128 + tid] = bo0[tid];
        sBias[2 * 128 + tid] = bq1[tid];
        sBias[3 * 128 + tid] = bk1[tid];
        sBias[4 * 128 + tid] = bv1[tid];
        sBias[5 * 128 + tid] = bo1[tid];
    }
    if (tid < 512) sIq[tid] = g_Iq[tid];
    if (tid < 16) sIqb[tid] = g_Iqb[tid];
    for (int i = tid; i < 768; i += NTH) sWo[i] = Wout[i];
    if (tid < 6) sWo[768 + tid] = bout[tid];

    lw_issueP(sm, sb, tid);          // stage folded P (8KB) into W buffer

    // gather -> X images
    for (int r = wid; r < ROWS; r += 16) {
        int n = member_idx[rowbase + r];
        if (n < 0) n = 0;
        if (n >= n_nodes) n = n_nodes - 1;
        float4 v = *(const float4*)(vfeat + (size_t)n * D_DIM + lane * 4);
        img_st4(sm, r, lane * 4, v);
    }
    cp_wait();
    __syncthreads();

    const int l4 = lane >> 2, c2 = (lane & 3) * 2;
    const int rg = wid >> 1, cg = wid & 1;
    const int lr = lane & 15, lh = lane >> 4;
    const int bn = (lane & 7) + ((lane >> 4) << 3);
    const int bh2 = (lane >> 3) & 1;

    float acc[8][4];
    float acc32[2][4];

    // ===== scores0 = X @ P (+Iqb)*SCALE  (128x16x128 mini-gemm) =====
    {
        float aS[4] = {0.f, 0.f, 0.f, 0.f};
        const int cgh = wid & 1;     // col half: 8 of 16 cols
#pragma unroll
        for (int ks = 0; ks < 8; ks++) {
            uint32_t ah[4], al[4];
            int r = rg * 16 + lr;
            uint32_t off = (uint32_t)(r * 256 + (((ks * 2 + lh) ^ (r & 7)) << 4));
            ldsm4(ah, xh + off);
            ldsm4(al, xl + off);
            uint32_t boff = (uint32_t)(bn * 256 + (((ks * 2 + bh2) ^ (bn & 7)) << 4));
            uint32_t bh[4], bl[4];
            ldsm4(bh, wh + boff);
            ldsm4(bl, wl + boff);
            uint32_t b0h = bh[2 * cgh], b1h = bh[2 * cgh + 1];
            uint32_t b0l = bl[2 * cgh], b1l = bl[2 * cgh + 1];
            mma16816(aS, ah, b0h, b1h);
            mma16816(aS, al, b0h, b1h);
            mma16816(aS, ah, b0l, b1l);
        }
        // scatter: rows r0,r0+8; cols j,j+1 (j even); n = h*4+qi
        int r0 = rg * 16 + l4;
        int j = cgh * 8 + c2;
        int h = j >> 2, qi0 = j & 3, qi1 = (j + 1) & 3;
        float b0 = sIqb[qi0 * 4 + h], b1 = sIqb[qi1 * 4 + h];
        {
            int e = r0 >> 4, s = r0 & 15;
            sScr[((e * 4 + h) * 4 + qi0) * 16 + s] = (aS[0] + b0) * SCALE_INV;
            sScr[((e * 4 + h) * 4 + qi1) * 16 + s] = (aS[1] + b1) * SCALE_INV;
            int e2 = (r0 + 8) >> 4, s2 = (r0 + 8) & 15;
            sScr[((e2 * 4 + h) * 4 + qi0) * 16 + s2] = (aS[2] + b0) * SCALE_INV;
            sScr[((e2 * 4 + h) * 4 + qi1) * 16 + s2] = (aS[3] + b1) * SCALE_INV;
        }
    }
    __syncthreads();                 // scores visible; P reads done
    lw_issue(sm, sb, 1, tid);        // stage Wv0

    if (tid < 128) {                 // softmax0, float4 row access
        float4* p4 = (float4*)&sScr[tid * 16];
        float4 a = p4[0], b = p4[1], c = p4[2], d = p4[3];
        float mx = fmaxf(fmaxf(fmaxf(a.x, a.y), fmaxf(a.z, a.w)),
                   fmaxf(fmaxf(fmaxf(b.x, b.y), fmaxf(b.z, b.w)),
                   fmaxf(fmaxf(fmaxf(c.x, c.y), fmaxf(c.z, c.w)),
                         fmaxf(fmaxf(d.x, d.y), fmaxf(d.z, d.w)))));
        a.x = expf(a.x - mx); a.y = expf(a.y - mx); a.z = expf(a.z - mx); a.w = expf(a.w - mx);
        b.x = expf(b.x - mx); b.y = expf(b.y - mx); b.z = expf(b.z - mx); b.w = expf(b.w - mx);
        c.x = expf(c.x - mx); c.y = expf(c.y - mx); c.z = expf(c.z - mx); c.w = expf(c.w - mx);
        d.x = expf(d.x - mx); d.y = expf(d.y - mx); d.z = expf(d.z - mx); d.w = expf(d.w - mx);
        float sum = a.x + a.y + a.z + a.w + b.x + b.y + b.z + b.w
                  + c.x + c.y + c.z + c.w + d.x + d.y + d.z + d.w;
        float inv = 1.f / sum;
        a.x *= inv; a.y *= inv; a.z *= inv; a.w *= inv;
        b.x *= inv; b.y *= inv; b.z *= inv; b.w *= inv;
        c.x *= inv; c.y *= inv; c.z *= inv; c.w *= inv;
        d.x *= inv; d.y *= inv; d.z *= inv; d.w *= inv;
        p4[0] = a; p4[1] = b; p4[2] = c; p4[3] = d;
    }
    cp_wait();
    __syncthreads();                 // softmax0 + Wv0 visible

    // ===== V0 = X@Wv0 + bv0 -> sF =====
#pragma unroll
    for (int j = 0; j < 8; j++)
#pragma unroll
        for (int q = 0; q < 4; q++) acc[j][q] = 0.f;
    gemm128(xh, xl, wh, wl, wid, lane, acc);
    {
        int r = rg * 16 + l4;
#pragma unroll
        for (int nt = 0; nt < 8; nt++) {
            int c = cg * 64 + nt * 8 + c2;
            *(float2*)&sF[r * SF_STR + c]       = make_float2(acc[nt][0] + sBias[c], acc[nt][1] + sBias[c + 1]);
            *(float2*)&sF[(r + 8) * SF_STR + c] = make_float2(acc[nt][2] + sBias[c], acc[nt][3] + sBias[c + 1]);
        }
    }
    __syncthreads();                 // V0f visible; Wv0 reads done
    lw_issue(sm, sb, 2, tid);        // stage Wq1

    // O0 = Iq + A @ V0f -> sSm (32 rows)
#pragma unroll
    for (int it = 0; it < 2; it++) {
        int idx = tid + it * 512;
        int d = (idx & 31) * 4, row = idx >> 5;
        int qi = row & 3, e = row >> 2, h = d >> 5;
        float4 o = *(const float4*)&sIq[qi * 128 + d];
        const float* A = &sScr[((e * 4 + h) * 4 + qi) * 16];
        const float* vv = &sF[(e * 16) * SF_STR + d];
#pragma unroll
        for (int s = 0; s < 16; s++) {
            float4 v = *(const float4*)&vv[s * SF_STR];
            float a = A[s];
            o.x += a * v.x; o.y += a * v.y; o.z += a * v.z; o.w += a * v.w;
        }
        *(float4*)&sSm[row * SF_STR + d] = o;
    }
    cp_wait();
    __syncthreads();

    // ===== Q1 = X@Wq1 + bq1 -> sF =====
#pragma unroll
    for (int j = 0; j < 8; j++)
#pragma unroll
        for (int q = 0; q < 4; q++) acc[j][q] = 0.f;
    gemm128(xh, xl, wh, wl, wid, lane, acc);
    {
        int r = rg * 16 + l4;
#pragma unroll
        for (int nt = 0; nt < 8; nt++) {
            int c = cg * 64 + nt * 8 + c2;
            *(float2*)&sF[r * SF_STR + c]       = make_float2(acc[nt][0] + sBias[2 * 128 + c], acc[nt][1] + sBias[2 * 128 + c + 1]);
            *(float2*)&sF[(r + 8) * SF_STR + c] = make_float2(acc[nt][2] + sBias[2 * 128 + c], acc[nt][3] + sBias[2 * 128 + c + 1]);
        }
    }
    __syncthreads();                 // X dead
    lw_issue(sm, sb, 3, tid);        // stage Wo0
    // O0 -> X image rows 0..31
#pragma unroll
    for (int it = 0; it < 2; it++) {
        int i = tid + it * 512;
        int r = i >> 5, c = (i & 31) * 4;
        img_st4(sm, r, c, *(const float4*)&sSm[r * SF_STR + c]);
    }
    cp_wait();
    __syncthreads();

    // ===== T0 = O0@Wo0 ; Hset -> image rows 0..31 =====
    acc32[0][0] = acc32[0][1] = acc32[0][2] = acc32[0][3] = 0.f;
    acc32[1][0] = acc32[1][1] = acc32[1][2] = acc32[1][3] = 0.f;
    gemm32(xh, xl, wh, wl, wid, lane, acc32);
    __syncthreads();
    lw_issue(sm, sb, 4, tid);        // stage Wk1
    {
        int rt = wid >> 3, cg8 = wid & 7;
        int r = rt * 16 + l4;
#pragma unroll
        for (int nt = 0; nt < 2; nt++) {
            int c = cg8 * 16 + nt * 8 + c2;
            float v0 = sSm[r * SF_STR + c]     + fmaxf(acc32[nt][0] + sBias[128 + c], 0.f);
            float v1 = sSm[r * SF_STR + c + 1] + fmaxf(acc32[nt][1] + sBias[128 + c + 1], 0.f);
            int i0 = imgoff(r, c);
            *(uint32_t*)(sm + OFF_XH + i0) = bf2bits(v0, v1);
            float h0 = __bfloat162float(__float2bfloat16(v0));
            float h1 = __bfloat162float(__float2bfloat16(v1));
            *(uint32_t*)(sm + OFF_XL + i0) = bf2bits(v0 - h0, v1 - h1);
            float w0 = sSm[(r + 8) * SF_STR + c]     + fmaxf(acc32[nt][2] + sBias[128 + c], 0.f);
            float w1 = sSm[(r + 8) * SF_STR + c + 1] + fmaxf(acc32[nt][3] + sBias[128 + c + 1], 0.f);
            int i1 = imgoff(r + 8, c);
            *(uint32_t*)(sm + OFF_XH + i1) = bf2bits(w0, w1);
            float g0 = __bfloat162float(__float2bfloat16(w0));
            float g1 = __bfloat162float(__float2bfloat16(w1));
            *(uint32_t*)(sm + OFF_XL + i1) = bf2bits(w0 - g0, w1 - g1);
        }
    }
    cp_wait();
    __syncthreads();                 // Hset image + Wk1 visible

    // ===== K1 = Hset@Wk1 + bk1 -> sK1 =====
    acc32[0][0] = acc32[0][1] = acc32[0][2] = acc32[0][3] = 0.f;
    acc32[1][0] = acc32[1][1] = acc32[1][2] = acc32[1][3] = 0.f;
    gemm32(xh, xl, wh, wl, wid, lane, acc32);
    {
        int rt = wid >> 3, cg8 = wid & 7;
        int r = rt * 16 + l4;
#pragma unroll
        for (int nt = 0; nt < 2; nt++) {
            int c = cg8 * 16 + nt * 8 + c2;
            *(float2*)&sK1[r * SF_STR + c]       = make_float2(acc32[nt][0] + sBias[3 * 128 + c], acc32[nt][1] + sBias[3 * 128 + c + 1]);
            *(float2*)&sK1[(r + 8) * SF_STR + c] = make_float2(acc32[nt][2] + sBias[3 * 128 + c], acc32[nt][3] + sBias[3 * 128 + c + 1]);
        }
    }
    __syncthreads();                 // Wk1 reads done; sK1 visible
    lw_issue(sm, sb, 5, tid);        // stage Wv1 — overlapped by scores1

    // scores1 (reads sF=Q1, sK1)
#pragma unroll
    for (int it = 0; it < 4; it++) {
        int idx = tid + it * 512;
        int k = idx & 3, q = (idx >> 2) & 15, h = (idx >> 6) & 3, e = idx >> 8;
        const float4* qv = (const float4*)&sF[(e * 16 + q) * SF_STR + h * 32];
        const float4* kv = (const float4*)&sK1[(e * 4 + k) * SF_STR + h * 32];
        float dot = 0.f;
#pragma unroll
        for (int d4 = 0; d4 < 8; d4++) {
            float4 qq = qv[d4], kk = kv[d4];
            dot += qq.x * kk.x + qq.y * kk.y + qq.z * kk.z + qq.w * kk.w;
        }
        sScr[idx] = dot * SCALE_INV;
    }
    cp_wait();
    __syncthreads();                 // scores1 + Wv1 visible

    // ===== V1 = Hset@Wv1 + bv1 -> sSm ; softmax1 =====
    acc32[0][0] = acc32[0][1] = acc32[0][2] = acc32[0][3] = 0.f;
    acc32[1][0] = acc32[1][1] = acc32[1][2] = acc32[1][3] = 0.f;
    gemm32(xh, xl, wh, wl, wid, lane, acc32);
    {
        int rt = wid >> 3, cg8 = wid & 7;
        int r = rt * 16 + l4;
#pragma unroll
        for (int nt = 0; nt < 2; nt++) {
            int c = cg8 * 16 + nt * 8 + c2;
            *(float2*)&sSm[r * SF_STR + c]       = make_float2(acc32[nt][0] + sBias[4 * 128 + c], acc32[nt][1] + sBias[4 * 128 + c + 1]);
            *(float2*)&sSm[(r + 8) * SF_STR + c] = make_float2(acc32[nt][2] + sBias[4 * 128 + c], acc32[nt][3] + sBias[4 * 128 + c + 1]);
        }
    }
    {   // softmax1: 512 rows (sScr only — disjoint)
        float* p = &sScr[tid * 4];
        float mx = fmaxf(fmaxf(p[0], p[1]), fmaxf(p[2], p[3]));
        float e0 = expf(p[0] - mx), e1 = expf(p[1] - mx), e2 = expf(p[2] - mx), e3 = expf(p[3] - mx);
        float inv = 1.f / (e0 + e1 + e2 + e3);
        p[0] = e0 * inv; p[1] = e1 * inv; p[2] = e2 * inv; p[3] = e3 * inv;
    }
    __syncthreads();                 // V1f + softmax1 visible; Wv1 reads done
    lw_issue(sm, sb, 6, tid);        // stage Wo1 — overlapped by O-update

    // O = Q1 + A1@V1f, fused sF update + X image write (K1f dead)
#pragma unroll
    for (int it = 0; it < 8; it++) {
        int idx = tid + it * 512;
        int d = (idx & 31) * 4, row = idx >> 5;
        int q = row & 15, e = row >> 4, h = d >> 5;
        float4 o = *(const float4*)&sF[row * SF_STR + d];
        const float* A = &sScr[((e * 4 + h) * 16 + q) * 4];
#pragma unroll
        for (int k = 0; k < 4; k++) {
            float4 v = *(const float4*)&sSm[(e * 4 + k) * SF_STR + d];
            float a = A[k];
            o.x += a * v.x; o.y += a * v.y; o.z += a * v.z; o.w += a * v.w;
        }
        *(float4*)&sF[row * SF_STR + d] = o;
        img_st4(sm, row, d, o);
    }
    cp_wait();
    __syncthreads();                 // O image + Wo1 visible

    // ===== T1 = O@Wo1 ; final -> sF in place =====
#pragma unroll
    for (int j = 0; j < 8; j++)
#pragma unroll
        for (int q = 0; q < 4; q++) acc[j][q] = 0.f;
    gemm128(xh, xl, wh, wl, wid, lane, acc);
    {
        int r = rg * 16 + l4;
#pragma unroll
        for (int nt = 0; nt < 8; nt++) {
            int c = cg * 64 + nt * 8 + c2;
            float2 s0 = *(const float2*)&sF[r * SF_STR + c];
            float2 s1 = *(const float2*)&sF[(r + 8) * SF_STR + c];
            s0.x += fmaxf(acc[nt][0] + sBias[5 * 128 + c], 0.f);
            s0.y += fmaxf(acc[nt][1] + sBias[5 * 128 + c + 1], 0.f);
            s1.x += fmaxf(acc[nt][2] + sBias[5 * 128 + c], 0.f);
            s1.y += fmaxf(acc[nt][3] + sBias[5 * 128 + c + 1], 0.f);
            *(float2*)&sF[r * SF_STR + c]       = s0;
            *(float2*)&sF[(r + 8) * SF_STR + c] = s1;
        }
    }
    __syncthreads();

    // logits: first 256 threads, 2 per row x 3 cols
    if (tid < 256) {
        int r = tid >> 1, cb = (tid & 1) * 3;
        float a0 = sWo[768 + cb], a1 = sWo[768 + cb + 1], a2 = sWo[768 + cb + 2];
        const float4* xr = (const float4*)&sF[r * SF_STR];
#pragma unroll
        for (int k4 = 0; k4 < 32; k4++) {
            float4 x = xr[k4];
            const float* w0 = &sWo[(k4 * 4 + 0) * C_CLS + cb];
            const float* w1 = &sWo[(k4 * 4 + 1) * C_CLS + cb];
            const float* w2 = &sWo[(k4 * 4 + 2) * C_CLS + cb];
            const float* w3 = &sWo[(k4 * 4 + 3) * C_CLS + cb];
            a0 += x.x * w0[0] + x.y * w1[0] + x.z * w2[0] + x.w * w3[0];
            a1 += x.x * w0[1] + x.y * w1[1] + x.z * w2[1] + x.w * w3[1];
            a2 += x.x * w0[2] + x.y * w1[2] + x.z * w2[2] + x.w * w3[2];
        }
        long long off = (long long)(rowbase + r) * C_CLS + cb;
        if (off + 2 < out_capacity) {
            out[off] = a0; out[off + 1] = a1; out[off + 2] = a2;
        }
    }
    long long lab_base = (long long)E_EDGES * S_MEM * C_CLS;
    if (out_capacity >= lab_base + (long long)E_EDGES * S_MEM && tid < ROWS) {
        out[lab_base + rowbase + tid] = (float)labels[rowbase + tid];
    }
}

extern "C" void kernel_launch(void* const* d_in, const int* in_sizes, int n_in,
                              void* d_out, int out_size) {
    const float* Ws[8] = {0,0,0,0,0,0,0,0};
    const float* Bs[8] = {0,0,0,0,0,0,0,0};
    const float* vfeat = 0; const float* Iin = 0;
    const float* Wout = 0;  const float* bout = 0;
    const int* member_idx = 0; const int* labels = 0;
    int wi = 0, bi = 0, n_nodes = 500000;
    for (int i = 0; i < n_in; i++) {
        int sz = in_sizes[i];
        if (sz == 500000 * 128)      { vfeat = (const float*)d_in[i]; n_nodes = sz / D_DIM; }
        else if (sz == E_EDGES * S_MEM) {
            if (!member_idx) member_idx = (const int*)d_in[i];
            else if (!labels) labels = (const int*)d_in[i];
        }
        else if (sz == M_IND * D_DIM) Iin = (const float*)d_in[i];
        else if (sz == D_DIM * C_CLS) Wout = (const float*)d_in[i];
        else if (sz == C_CLS)         bout = (const float*)d_in[i];
        else if (sz == D_DIM * D_DIM) { if (wi < 8) Ws[wi++] = (const float*)d_in[i]; }
        else if (sz == D_DIM)         { if (bi < 8) Bs[bi++] = (const float*)d_in[i]; }
    }
    if (!vfeat || !member_idx || !labels || !Iin || !Wout || !bout || wi != 8 || bi != 8) {
        vfeat = (const float*)d_in[0]; member_idx = (const int*)d_in[1];
        labels = (const int*)d_in[2];  Iin = (const float*)d_in[3];
        Wout = (const float*)d_in[4];  bout = (const float*)d_in[5];
        for (int j = 0; j < 8; j++) { Ws[j] = (const float*)d_in[6 + 2 * j]; Bs[j] = (const float*)d_in[7 + 2 * j]; }
        n_nodes = in_sizes[0] / D_DIM;
    }
    const float *Wq0 = Ws[0], *Wk0 = Ws[1], *Wv0 = Ws[2], *Wo0 = Ws[3];
    const float *Wq1 = Ws[4], *Wk1 = Ws[5], *Wv1 = Ws[6], *Wo1 = Ws[7];
    const float *bq0 = Bs[0], *bk0 = Bs[1], *bv0 = Bs[2], *bo0 = Bs[3];
    const float *bq1 = Bs[4], *bk1 = Bs[5], *bv1 = Bs[6], *bo1 = Bs[7];

    cudaFuncSetAttribute(whatsnet_mma, cudaFuncAttributeMaxDynamicSharedMemorySize, SMEM_TOTAL);

    iq_kernel<<<2, 256>>>(Iin, Wq0, bq0);
    iqb_kernel<<<1, 32>>>(bk0);
    p_kernel<<<8, 256>>>(Wk0);
    wconv_kernel<<<7, 256>>>(Wk0, Wv0, Wq1, Wo0, Wk1, Wv1, Wo1);

    whatsnet_mma<<<E_EDGES * S_MEM / ROWS, NTH, SMEM_TOTAL>>>(
        vfeat, member_idx, labels, Wout, bout,
        bv0, bo0, bq1, bk1, bv1, bo1,
        (float*)d_out, n_nodes, (long long)out_size);
}

// round 17
// speedup vs baseline: 1.6578x; 1.0202x over previous
#include <cuda_runtime.h>
#include <cuda_bf16.h>
#include <math.h>
#include <stdint.h>

#define E_EDGES 100000
#define S_MEM   16
#define D_DIM   128
#define C_CLS   6
#define M_IND   4
#define ROWS    128
#define NTH     512
#define SCALE_INV 0.08838834764831845f

// SMEM byte offsets
#define OFF_XH  0
#define OFF_XL  32768
#define OFF_WH  65536
#define OFF_WL  98304
#define OFF_SF  131072                 // f32 [128][132]
#define SF_STR  132
#define OFF_SSM (OFF_SF + 128*SF_STR*4)    // f32 [32][132]
#define OFF_BIAS (OFF_SSM + 32*SF_STR*4)   // f32 [6][128]
#define OFF_IQ  (OFF_BIAS + 6*128*4)       // f32 [512]
#define OFF_IQB (OFF_IQ + 2048)            // f32 [16]
#define OFF_WOUT (OFF_IQB + 64)            // f32 [776]
#define OFF_SCR (OFF_WOUT + 3104)          // f32 [2048]
#define SMEM_TOTAL (OFF_SCR + 8192)        // 232032 <= 232448

__device__ __align__(16) float g_Iq[M_IND * D_DIM];
__device__ __align__(16) float g_Iqb[16];
__device__ __align__(16) __nv_bfloat16 g_WH[7][16384];
__device__ __align__(16) __nv_bfloat16 g_WL[7][16384];
// folded scores weight P[n][k], n = h*4+qi (16 rows), frag layout like g_WH rows
__device__ __align__(16) __nv_bfloat16 g_PH[2048];
__device__ __align__(16) __nv_bfloat16 g_PL[2048];

__host__ __device__ __forceinline__ int imgoff(int r, int c) {
    return r * 256 + (((c >> 3) ^ (r & 7)) << 4) + ((c & 7) << 1);
}

__device__ __forceinline__ uint32_t cvta_s(const void* p) {
    uint32_t a;
    asm("{ .reg .u64 t; cvta.to.shared.u64 t, %1; cvt.u32.u64 %0, t; }" : "=r"(a) : "l"(p));
    return a;
}
__device__ __forceinline__ void ldsm4(uint32_t* a, uint32_t addr) {
    asm volatile("ldmatrix.sync.aligned.m8n8.x4.shared.b16 {%0,%1,%2,%3}, [%4];"
        : "=r"(a[0]), "=r"(a[1]), "=r"(a[2]), "=r"(a[3]) : "r"(addr));
}
__device__ __forceinline__ void mma16816(float* c, const uint32_t* a, uint32_t b0, uint32_t b1) {
    asm volatile("mma.sync.aligned.m16n8k16.row.col.f32.bf16.bf16.f32 "
        "{%0,%1,%2,%3}, {%4,%5,%6,%7}, {%8,%9}, {%0,%1,%2,%3};"
        : "+f"(c[0]), "+f"(c[1]), "+f"(c[2]), "+f"(c[3])
        : "r"(a[0]), "r"(a[1]), "r"(a[2]), "r"(a[3]), "r"(b0), "r"(b1));
}
__device__ __forceinline__ void cp16(uint32_t dst, const void* src) {
    asm volatile("cp.async.cg.shared.global [%0], [%1], 16;" :: "r"(dst), "l"(src) : "memory");
}
__device__ __forceinline__ void cp_commit() { asm volatile("cp.async.commit_group;" ::: "memory"); }
__device__ __forceinline__ void cp_wait()   { asm volatile("cp.async.wait_group 0;" ::: "memory"); }

__device__ __forceinline__ uint32_t bf2bits(float a, float b) {
    __nv_bfloat162 p; p.x = __float2bfloat16(a); p.y = __float2bfloat16(b);
    return *(uint32_t*)&p;
}
__device__ __forceinline__ void img_st4(char* sm, int r, int c, float4 v) {
    int i = imgoff(r, c);
    float hx = __bfloat162float(__float2bfloat16(v.x));
    float hy = __bfloat162float(__float2bfloat16(v.y));
    float hz = __bfloat162float(__float2bfloat16(v.z));
    float hw = __bfloat162float(__float2bfloat16(v.w));
    uint2 hh, ll;
    hh.x = bf2bits(v.x, v.y);      hh.y = bf2bits(v.z, v.w);
    ll.x = bf2bits(v.x - hx, v.y - hy);
    ll.y = bf2bits(v.z - hz, v.w - hw);
    *(uint2*)(sm + OFF_XH + i) = hh;
    *(uint2*)(sm + OFF_XL + i) = ll;
}

// ---------------- prologs ----------------
__global__ void iq_kernel(const float* __restrict__ I, const float* __restrict__ Wq,
                          const float* __restrict__ bq) {
    int idx = blockIdx.x * blockDim.x + threadIdx.x;
    if (idx >= M_IND * D_DIM) return;
    int qi = idx / D_DIM, d = idx % D_DIM;
    float acc = bq[d];
    for (int k = 0; k < D_DIM; k++) acc += I[qi * D_DIM + k] * Wq[k * D_DIM + d];
    g_Iq[idx] = acc;
}
__global__ void iqb_kernel(const float* __restrict__ bk0) {
    int t = threadIdx.x;
    if (t < 16) {
        int qi = t >> 2, h = t & 3;
        float s = 0.f;
        for (int j = 0; j < 32; j++) s += g_Iq[qi * 128 + h * 32 + j] * bk0[h * 32 + j];
        g_Iqb[t] = s;
    }
}
// P[n=h*4+qi][k] = sum_{j<32} Wk0[k][h*32+j] * Iq[qi][h*32+j]; frag-image layout
__global__ void p_kernel(const float* __restrict__ Wk0) {
    int t = blockIdx.x * blockDim.x + threadIdx.x;
    if (t >= 2048) return;
    int n = t >> 7, k = t & 127;
    int h = n >> 2, qi = n & 3;
    float p = 0.f;
    for (int j = 0; j < 32; j++) p += Wk0[k * 128 + h * 32 + j] * g_Iq[qi * 128 + h * 32 + j];
    __nv_bfloat16 hh = __float2bfloat16(p);
    int idx = n * 128 + (((k >> 3) ^ (n & 7)) << 3) + (k & 7);
    g_PH[idx] = hh;
    g_PL[idx] = __float2bfloat16(p - __bfloat162float(hh));
}
__global__ void wconv_kernel(const float* W0, const float* W1, const float* W2, const float* W3,
                             const float* W4, const float* W5, const float* W6) {
    const float* W;
    int m = blockIdx.x;
    switch (m) { case 0: W = W0; break; case 1: W = W1; break; case 2: W = W2; break;
                 case 3: W = W3; break; case 4: W = W4; break; case 5: W = W5; break;
                 default: W = W6; }
    for (int i = threadIdx.x; i < 16384; i += blockDim.x) {
        int n = i >> 7, k = i & 127;
        float w = W[k * 128 + n];
        __nv_bfloat16 h = __float2bfloat16(w);
        int idx = n * 128 + (((k >> 3) ^ (n & 7)) << 3) + (k & 7);
        g_WH[m][idx] = h;
        g_WL[m][idx] = __float2bfloat16(w - __bfloat162float(h));
    }
}

__device__ __forceinline__ void lw_issue(char* sm, uint32_t sb, int widx, int tid) {
    const char* gh = (const char*)g_WH[widx];
    const char* gl = (const char*)g_WL[widx];
    uint32_t dh = sb + OFF_WH, dl = sb + OFF_WL;
#pragma unroll
    for (int i = 0; i < 4; i++) {
        int off = (tid + i * 512) * 16;
        cp16(dh + off, gh + off);
        cp16(dl + off, gl + off);
    }
    cp_commit();
}
__device__ __forceinline__ void lw_issueP(char* sm, uint32_t sb, int tid) {
    if (tid < 256) cp16(sb + OFF_WH + tid * 16, (const char*)g_PH + tid * 16);
    else if (tid < 512) cp16(sb + OFF_WL + (tid - 256) * 16, (const char*)g_PL + (tid - 256) * 16);
    cp_commit();
}

// 128x128x128 GEMM, 16 warps: rowgroup wid>>1 (16 rows), colgroup wid&1 (64 cols)
// [round-13 mapping — 4x4 remap regressed 49% (round 14); do not change]
__device__ __forceinline__ void gemm128(uint32_t xh, uint32_t xl, uint32_t wh, uint32_t wl,
                                        int wid, int lane, float acc[8][4]) {
    const int rg = wid >> 1, cg = wid & 1;
    const int lr = lane & 15, lh = lane >> 4;
    const int bn = (lane & 7) + ((lane >> 4) << 3);
    const int bh2 = (lane >> 3) & 1;
#pragma unroll
    for (int ks = 0; ks < 8; ks++) {
        uint32_t ah[4], al[4];
        int r = rg * 16 + lr;
        uint32_t off = (uint32_t)(r * 256 + (((ks * 2 + lh) ^ (r & 7)) << 4));
        ldsm4(ah, xh + off);
        ldsm4(al, xl + off);
#pragma unroll
        for (int ntp = 0; ntp < 4; ntp++) {
            int n = cg * 64 + ntp * 16 + bn;
            uint32_t boff = (uint32_t)(n * 256 + (((ks * 2 + bh2) ^ (n & 7)) << 4));
            uint32_t bh[4], bl[4];
            ldsm4(bh, wh + boff);
            ldsm4(bl, wl + boff);
            mma16816(acc[2 * ntp],     ah, bh[0], bh[1]);
            mma16816(acc[2 * ntp],     al, bh[0], bh[1]);
            mma16816(acc[2 * ntp],     ah, bl[0], bl[1]);
            mma16816(acc[2 * ntp + 1], ah, bh[2], bh[3]);
            mma16816(acc[2 * ntp + 1], al, bh[2], bh[3]);
            mma16816(acc[2 * ntp + 1], ah, bl[2], bl[3]);
        }
    }
}

// 32x128x128 GEMM, 16 warps
__device__ __forceinline__ void gemm32(uint32_t xh, uint32_t xl, uint32_t wh, uint32_t wl,
                                       int wid, int lane, float acc[2][4]) {
    const int rt = wid >> 3, cg8 = wid & 7;
    const int lr = lane & 15, lh = lane >> 4;
    const int bn = (lane & 7) + ((lane >> 4) << 3);
    const int bh2 = (lane >> 3) & 1;
#pragma unroll
    for (int ks = 0; ks < 8; ks++) {
        uint32_t ah[4], al[4];
        int r = rt * 16 + lr;
        uint32_t off = (uint32_t)(r * 256 + (((ks * 2 + lh) ^ (r & 7)) << 4));
        ldsm4(ah, xh + off);
        ldsm4(al, xl + off);
        int n = cg8 * 16 + bn;
        uint32_t boff = (uint32_t)(n * 256 + (((ks * 2 + bh2) ^ (n & 7)) << 4));
        uint32_t bh[4], bl[4];
        ldsm4(bh, wh + boff);
        ldsm4(bl, wl + boff);
        mma16816(acc[0], ah, bh[0], bh[1]);
        mma16816(acc[0], al, bh[0], bh[1]);
        mma16816(acc[0], ah, bl[0], bl[1]);
        mma16816(acc[1], ah, bh[2], bh[3]);
        mma16816(acc[1], al, bh[2], bh[3]);
        mma16816(acc[1], ah, bl[2], bl[3]);
    }
}

extern "C" __global__ void __launch_bounds__(NTH, 1)
whatsnet_mma(const float* __restrict__ vfeat, const int* __restrict__ member_idx,
             const int* __restrict__ labels,
             const float* __restrict__ Wout, const float* __restrict__ bout,
             const float* __restrict__ bv0, const float* __restrict__ bo0,
             const float* __restrict__ bq1, const float* __restrict__ bk1,
             const float* __restrict__ bv1, const float* __restrict__ bo1,
             float* __restrict__ out, int n_nodes, long long out_capacity)
{
    extern __shared__ char sm[];
    const int tid = threadIdx.x;
    const int wid = tid >> 5, lane = tid & 31;
    const int rowbase = blockIdx.x * ROWS;
    const uint32_t sb = cvta_s(sm);
    const uint32_t xh = sb + OFF_XH, xl = sb + OFF_XL;
    const uint32_t wh = sb + OFF_WH, wl = sb + OFF_WL;

    float* sF   = (float*)(sm + OFF_SF);
    float* sSm  = (float*)(sm + OFF_SSM);     // O0; later V1f
    float* sK1  = (float*)(sm + OFF_XH + 8704);
    float* sBias= (float*)(sm + OFF_BIAS);
    float* sIq  = (float*)(sm + OFF_IQ);
    float* sIqb = (float*)(sm + OFF_IQB);
    float* sWo  = (float*)(sm + OFF_WOUT);
    float* sScr = (float*)(sm + OFF_SCR);

    // constants
    if (tid < 128) {
        sBias[0 * 128 + tid] = bv0[tid];
        sBias[1 * 128 + tid] = bo0[tid];
        sBias[2 * 128 + tid] = bq1[tid];
        sBias[3 * 128 + tid] = bk1[tid];
        sBias[4 * 128 + tid] = bv1[tid];
        sBias[5 * 128 + tid] = bo1[tid];
    }
    if (tid < 512) sIq[tid] = g_Iq[tid];
    if (tid < 16) sIqb[tid] = g_Iqb[tid];
    for (int i = tid; i < 768; i += NTH) sWo[i] = Wout[i];
    if (tid < 6) sWo[768 + tid] = bout[tid];

    lw_issueP(sm, sb, tid);          // stage folded P (8KB) into W buffer

    // gather -> X images
    for (int r = wid; r < ROWS; r += 16) {
        int n = member_idx[rowbase + r];
        if (n < 0) n = 0;
        if (n >= n_nodes) n = n_nodes - 1;
        float4 v = *(const float4*)(vfeat + (size_t)n * D_DIM + lane * 4);
        img_st4(sm, r, lane * 4, v);
    }
    cp_wait();
    __syncthreads();

    const int l4 = lane >> 2, c2 = (lane & 3) * 2;
    const int rg = wid >> 1, cg = wid & 1;
    const int lr = lane & 15, lh = lane >> 4;
    const int bn = (lane & 7) + ((lane >> 4) << 3);
    const int bh2 = (lane >> 3) & 1;

    float acc[8][4];
    float acc32[2][4];

    // ===== scores0 = X @ P (+Iqb)*SCALE  (128x16x128 mini-gemm) =====
    {
        float aS[4] = {0.f, 0.f, 0.f, 0.f};
        const int cgh = wid & 1;     // col half: 8 of 16 cols
#pragma unroll
        for (int ks = 0; ks < 8; ks++) {
            uint32_t ah[4], al[4];
            int r = rg * 16 + lr;
            uint32_t off = (uint32_t)(r * 256 + (((ks * 2 + lh) ^ (r & 7)) << 4));
            ldsm4(ah, xh + off);
            ldsm4(al, xl + off);
            uint32_t boff = (uint32_t)(bn * 256 + (((ks * 2 + bh2) ^ (bn & 7)) << 4));
            uint32_t bh[4], bl[4];
            ldsm4(bh, wh + boff);
            ldsm4(bl, wl + boff);
            uint32_t b0h = bh[2 * cgh], b1h = bh[2 * cgh + 1];
            uint32_t b0l = bl[2 * cgh], b1l = bl[2 * cgh + 1];
            mma16816(aS, ah, b0h, b1h);
            mma16816(aS, al, b0h, b1h);
            mma16816(aS, ah, b0l, b1l);
        }
        int r0 = rg * 16 + l4;
        int j = cgh * 8 + c2;
        int h = j >> 2, qi0 = j & 3, qi1 = (j + 1) & 3;
        float b0 = sIqb[qi0 * 4 + h], b1 = sIqb[qi1 * 4 + h];
        {
            int e = r0 >> 4, s = r0 & 15;
            sScr[((e * 4 + h) * 4 + qi0) * 16 + s] = (aS[0] + b0) * SCALE_INV;
            sScr[((e * 4 + h) * 4 + qi1) * 16 + s] = (aS[1] + b1) * SCALE_INV;
            int e2 = (r0 + 8) >> 4, s2 = (r0 + 8) & 15;
            sScr[((e2 * 4 + h) * 4 + qi0) * 16 + s2] = (aS[2] + b0) * SCALE_INV;
            sScr[((e2 * 4 + h) * 4 + qi1) * 16 + s2] = (aS[3] + b1) * SCALE_INV;
        }
    }
    __syncthreads();                 // scores visible; P reads done
    lw_issue(sm, sb, 1, tid);        // stage Wv0

    if (tid < 128) {                 // softmax0, float4 row access
        float4* p4 = (float4*)&sScr[tid * 16];
        float4 a = p4[0], b = p4[1], c = p4[2], d = p4[3];
        float mx = fmaxf(fmaxf(fmaxf(a.x, a.y), fmaxf(a.z, a.w)),
                   fmaxf(fmaxf(fmaxf(b.x, b.y), fmaxf(b.z, b.w)),
                   fmaxf(fmaxf(fmaxf(c.x, c.y), fmaxf(c.z, c.w)),
                         fmaxf(fmaxf(d.x, d.y), fmaxf(d.z, d.w)))));
        a.x = expf(a.x - mx); a.y = expf(a.y - mx); a.z = expf(a.z - mx); a.w = expf(a.w - mx);
        b.x = expf(b.x - mx); b.y = expf(b.y - mx); b.z = expf(b.z - mx); b.w = expf(b.w - mx);
        c.x = expf(c.x - mx); c.y = expf(c.y - mx); c.z = expf(c.z - mx); c.w = expf(c.w - mx);
        d.x = expf(d.x - mx); d.y = expf(d.y - mx); d.z = expf(d.z - mx); d.w = expf(d.w - mx);
        float sum = a.x + a.y + a.z + a.w + b.x + b.y + b.z + b.w
                  + c.x + c.y + c.z + c.w + d.x + d.y + d.z + d.w;
        float inv = 1.f / sum;
        a.x *= inv; a.y *= inv; a.z *= inv; a.w *= inv;
        b.x *= inv; b.y *= inv; b.z *= inv; b.w *= inv;
        c.x *= inv; c.y *= inv; c.z *= inv; c.w *= inv;
        d.x *= inv; d.y *= inv; d.z *= inv; d.w *= inv;
        p4[0] = a; p4[1] = b; p4[2] = c; p4[3] = d;
    }
    cp_wait();
    __syncthreads();                 // softmax0 + Wv0 visible

    // ===== V0 = X@Wv0 + bv0 -> sF =====
#pragma unroll
    for (int j = 0; j < 8; j++)
#pragma unroll
        for (int q = 0; q < 4; q++) acc[j][q] = 0.f;
    gemm128(xh, xl, wh, wl, wid, lane, acc);
    {
        int r = rg * 16 + l4;
#pragma unroll
        for (int nt = 0; nt < 8; nt++) {
            int c = cg * 64 + nt * 8 + c2;
            *(float2*)&sF[r * SF_STR + c]       = make_float2(acc[nt][0] + sBias[c], acc[nt][1] + sBias[c + 1]);
            *(float2*)&sF[(r + 8) * SF_STR + c] = make_float2(acc[nt][2] + sBias[c], acc[nt][3] + sBias[c + 1]);
        }
    }
    __syncthreads();                 // V0f visible; Wv0 reads done
    lw_issue(sm, sb, 2, tid);        // stage Wq1

    // O0 = Iq + A @ V0f -> sSm (32 rows)
#pragma unroll
    for (int it = 0; it < 2; it++) {
        int idx = tid + it * 512;
        int d = (idx & 31) * 4, row = idx >> 5;
        int qi = row & 3, e = row >> 2, h = d >> 5;
        float4 o = *(const float4*)&sIq[qi * 128 + d];
        const float* A = &sScr[((e * 4 + h) * 4 + qi) * 16];
        const float* vv = &sF[(e * 16) * SF_STR + d];
#pragma unroll
        for (int s = 0; s < 16; s++) {
            float4 v = *(const float4*)&vv[s * SF_STR];
            float a = A[s];
            o.x += a * v.x; o.y += a * v.y; o.z += a * v.z; o.w += a * v.w;
        }
        *(float4*)&sSm[row * SF_STR + d] = o;
    }
    cp_wait();
    __syncthreads();

    // ===== Q1 = X@Wq1 + bq1 -> sF =====
#pragma unroll
    for (int j = 0; j < 8; j++)
#pragma unroll
        for (int q = 0; q < 4; q++) acc[j][q] = 0.f;
    gemm128(xh, xl, wh, wl, wid, lane, acc);
    {
        int r = rg * 16 + l4;
#pragma unroll
        for (int nt = 0; nt < 8; nt++) {
            int c = cg * 64 + nt * 8 + c2;
            *(float2*)&sF[r * SF_STR + c]       = make_float2(acc[nt][0] + sBias[2 * 128 + c], acc[nt][1] + sBias[2 * 128 + c + 1]);
            *(float2*)&sF[(r + 8) * SF_STR + c] = make_float2(acc[nt][2] + sBias[2 * 128 + c], acc[nt][3] + sBias[2 * 128 + c + 1]);
        }
    }
    __syncthreads();                 // X dead
    lw_issue(sm, sb, 3, tid);        // stage Wo0
    // O0 -> X image rows 0..31
#pragma unroll
    for (int it = 0; it < 2; it++) {
        int i = tid + it * 512;
        int r = i >> 5, c = (i & 31) * 4;
        img_st4(sm, r, c, *(const float4*)&sSm[r * SF_STR + c]);
    }
    cp_wait();
    __syncthreads();

    // ===== T0 = O0@Wo0 ; Hset -> image rows 0..31 =====
    acc32[0][0] = acc32[0][1] = acc32[0][2] = acc32[0][3] = 0.f;
    acc32[1][0] = acc32[1][1] = acc32[1][2] = acc32[1][3] = 0.f;
    gemm32(xh, xl, wh, wl, wid, lane, acc32);
    __syncthreads();
    lw_issue(sm, sb, 4, tid);        // stage Wk1
    {
        int rt = wid >> 3, cg8 = wid & 7;
        int r = rt * 16 + l4;
#pragma unroll
        for (int nt = 0; nt < 2; nt++) {
            int c = cg8 * 16 + nt * 8 + c2;
            float v0 = sSm[r * SF_STR + c]     + fmaxf(acc32[nt][0] + sBias[128 + c], 0.f);
            float v1 = sSm[r * SF_STR + c + 1] + fmaxf(acc32[nt][1] + sBias[128 + c + 1], 0.f);
            int i0 = imgoff(r, c);
            *(uint32_t*)(sm + OFF_XH + i0) = bf2bits(v0, v1);
            float h0 = __bfloat162float(__float2bfloat16(v0));
            float h1 = __bfloat162float(__float2bfloat16(v1));
            *(uint32_t*)(sm + OFF_XL + i0) = bf2bits(v0 - h0, v1 - h1);
            float w0 = sSm[(r + 8) * SF_STR + c]     + fmaxf(acc32[nt][2] + sBias[128 + c], 0.f);
            float w1 = sSm[(r + 8) * SF_STR + c + 1] + fmaxf(acc32[nt][3] + sBias[128 + c + 1], 0.f);
            int i1 = imgoff(r + 8, c);
            *(uint32_t*)(sm + OFF_XH + i1) = bf2bits(w0, w1);
            float g0 = __bfloat162float(__float2bfloat16(w0));
            float g1 = __bfloat162float(__float2bfloat16(w1));
            *(uint32_t*)(sm + OFF_XL + i1) = bf2bits(w0 - g0, w1 - g1);
        }
    }
    cp_wait();
    __syncthreads();                 // Hset image + Wk1 visible

    // ===== K1 = Hset@Wk1 + bk1 -> sK1 =====
    acc32[0][0] = acc32[0][1] = acc32[0][2] = acc32[0][3] = 0.f;
    acc32[1][0] = acc32[1][1] = acc32[1][2] = acc32[1][3] = 0.f;
    gemm32(xh, xl, wh, wl, wid, lane, acc32);
    {
        int rt = wid >> 3, cg8 = wid & 7;
        int r = rt * 16 + l4;
#pragma unroll
        for (int nt = 0; nt < 2; nt++) {
            int c = cg8 * 16 + nt * 8 + c2;
            *(float2*)&sK1[r * SF_STR + c]       = make_float2(acc32[nt][0] + sBias[3 * 128 + c], acc32[nt][1] + sBias[3 * 128 + c + 1]);
            *(float2*)&sK1[(r + 8) * SF_STR + c] = make_float2(acc32[nt][2] + sBias[3 * 128 + c], acc32[nt][3] + sBias[3 * 128 + c + 1]);
        }
    }
    __syncthreads();                 // Wk1 reads done; sK1 visible
    lw_issue(sm, sb, 5, tid);        // stage Wv1 — overlapped by fused scores1

    // ===== scores1 + softmax1 fused: one thread per (e,h,q) = 512 =====
    {
        int q = tid & 15, h = (tid >> 4) & 3, e = tid >> 6;
        const float4* qv = (const float4*)&sF[(e * 16 + q) * SF_STR + h * 32];
        float4 qr[8];
#pragma unroll
        for (int d4 = 0; d4 < 8; d4++) qr[d4] = qv[d4];
        float dot[4];
#pragma unroll
        for (int k = 0; k < 4; k++) {
            const float4* kv = (const float4*)&sK1[(e * 4 + k) * SF_STR + h * 32];
            float s = 0.f;
#pragma unroll
            for (int d4 = 0; d4 < 8; d4++) {
                float4 kk = kv[d4];
                s += qr[d4].x * kk.x + qr[d4].y * kk.y + qr[d4].z * kk.z + qr[d4].w * kk.w;
            }
            dot[k] = s * SCALE_INV;
        }
        float mx = fmaxf(fmaxf(dot[0], dot[1]), fmaxf(dot[2], dot[3]));
        float e0 = expf(dot[0] - mx), e1 = expf(dot[1] - mx);
        float e2 = expf(dot[2] - mx), e3 = expf(dot[3] - mx);
        float inv = 1.f / (e0 + e1 + e2 + e3);
        float4 pr = make_float4(e0 * inv, e1 * inv, e2 * inv, e3 * inv);
        *(float4*)&sScr[((e * 4 + h) * 16 + q) * 4] = pr;
    }
    cp_wait();
    __syncthreads();                 // probs + Wv1 visible

    // ===== V1 = Hset@Wv1 + bv1 -> sSm =====
    acc32[0][0] = acc32[0][1] = acc32[0][2] = acc32[0][3] = 0.f;
    acc32[1][0] = acc32[1][1] = acc32[1][2] = acc32[1][3] = 0.f;
    gemm32(xh, xl, wh, wl, wid, lane, acc32);
    {
        int rt = wid >> 3, cg8 = wid & 7;
        int r = rt * 16 + l4;
#pragma unroll
        for (int nt = 0; nt < 2; nt++) {
            int c = cg8 * 16 + nt * 8 + c2;
            *(float2*)&sSm[r * SF_STR + c]       = make_float2(acc32[nt][0] + sBias[4 * 128 + c], acc32[nt][1] + sBias[4 * 128 + c + 1]);
            *(float2*)&sSm[(r + 8) * SF_STR + c] = make_float2(acc32[nt][2] + sBias[4 * 128 + c], acc32[nt][3] + sBias[4 * 128 + c + 1]);
        }
    }
    __syncthreads();                 // V1f visible; Wv1 reads done
    lw_issue(sm, sb, 6, tid);        // stage Wo1 — overlapped by O-update

    // O = Q1 + A1@V1f, fused sF update + X image write (K1f dead)
#pragma unroll
    for (int it = 0; it < 8; it++) {
        int idx = tid + it * 512;
        int d = (idx & 31) * 4, row = idx >> 5;
        int q = row & 15, e = row >> 4, h = d >> 5;
        float4 o = *(const float4*)&sF[row * SF_STR + d];
        const float* A = &sScr[((e * 4 + h) * 16 + q) * 4];
#pragma unroll
        for (int k = 0; k < 4; k++) {
            float4 v = *(const float4*)&sSm[(e * 4 + k) * SF_STR + d];
            float a = A[k];
            o.x += a * v.x; o.y += a * v.y; o.z += a * v.z; o.w += a * v.w;
        }
        *(float4*)&sF[row * SF_STR + d] = o;
        img_st4(sm, row, d, o);
    }
    cp_wait();
    __syncthreads();                 // O image + Wo1 visible

    // ===== T1 = O@Wo1 ; final -> sF in place =====
#pragma unroll
    for (int j = 0; j < 8; j++)
#pragma unroll
        for (int q = 0; q < 4; q++) acc[j][q] = 0.f;
    gemm128(xh, xl, wh, wl, wid, lane, acc);
    {
        int r = rg * 16 + l4;
#pragma unroll
        for (int nt = 0; nt < 8; nt++) {
            int c = cg * 64 + nt * 8 + c2;
            float2 s0 = *(const float2*)&sF[r * SF_STR + c];
            float2 s1 = *(const float2*)&sF[(r + 8) * SF_STR + c];
            s0.x += fmaxf(acc[nt][0] + sBias[5 * 128 + c], 0.f);
            s0.y += fmaxf(acc[nt][1] + sBias[5 * 128 + c + 1], 0.f);
            s1.x += fmaxf(acc[nt][2] + sBias[5 * 128 + c], 0.f);
            s1.y += fmaxf(acc[nt][3] + sBias[5 * 128 + c + 1], 0.f);
            *(float2*)&sF[r * SF_STR + c]       = s0;
            *(float2*)&sF[(r + 8) * SF_STR + c] = s1;
        }
    }
    __syncthreads();

    // logits: first 256 threads, 2 per row x 3 cols
    if (tid < 256) {
        int r = tid >> 1, cb = (tid & 1) * 3;
        float a0 = sWo[768 + cb], a1 = sWo[768 + cb + 1], a2 = sWo[768 + cb + 2];
        const float4* xr = (const float4*)&sF[r * SF_STR];
#pragma unroll
        for (int k4 = 0; k4 < 32; k4++) {
            float4 x = xr[k4];
            const float* w0 = &sWo[(k4 * 4 + 0) * C_CLS + cb];
            const float* w1 = &sWo[(k4 * 4 + 1) * C_CLS + cb];
            const float* w2 = &sWo[(k4 * 4 + 2) * C_CLS + cb];
            const float* w3 = &sWo[(k4 * 4 + 3) * C_CLS + cb];
            a0 += x.x * w0[0] + x.y * w1[0] + x.z * w2[0] + x.w * w3[0];
            a1 += x.x * w0[1] + x.y * w1[1] + x.z * w2[1] + x.w * w3[1];
            a2 += x.x * w0[2] + x.y * w1[2] + x.z * w2[2] + x.w * w3[2];
        }
        long long off = (long long)(rowbase + r) * C_CLS + cb;
        if (off + 2 < out_capacity) {
            out[off] = a0; out[off + 1] = a1; out[off + 2] = a2;
        }
    }
    long long lab_base = (long long)E_EDGES * S_MEM * C_CLS;
    if (out_capacity >= lab_base + (long long)E_EDGES * S_MEM && tid < ROWS) {
        out[lab_base + rowbase + tid] = (float)labels[rowbase + tid];
    }
}

extern "C" void kernel_launch(void* const* d_in, const int* in_sizes, int n_in,
                              void* d_out, int out_size) {
    const float* Ws[8] = {0,0,0,0,0,0,0,0};
    const float* Bs[8] = {0,0,0,0,0,0,0,0};
    const float* vfeat = 0; const float* Iin = 0;
    const float* Wout = 0;  const float* bout = 0;
    const int* member_idx = 0; const int* labels = 0;
    int wi = 0, bi = 0, n_nodes = 500000;
    for (int i = 0; i < n_in; i++) {
        int sz = in_sizes[i];
        if (sz == 500000 * 128)      { vfeat = (const float*)d_in[i]; n_nodes = sz / D_DIM; }
        else if (sz == E_EDGES * S_MEM) {
            if (!member_idx) member_idx = (const int*)d_in[i];
            else if (!labels) labels = (const int*)d_in[i];
        }
        else if (sz == M_IND * D_DIM) Iin = (const float*)d_in[i];
        else if (sz == D_DIM * C_CLS) Wout = (const float*)d_in[i];
        else if (sz == C_CLS)         bout = (const float*)d_in[i];
        else if (sz == D_DIM * D_DIM) { if (wi < 8) Ws[wi++] = (const float*)d_in[i]; }
        else if (sz == D_DIM)         { if (bi < 8) Bs[bi++] = (const float*)d_in[i]; }
    }
    if (!vfeat || !member_idx || !labels || !Iin || !Wout || !bout || wi != 8 || bi != 8) {
        vfeat = (const float*)d_in[0]; member_idx = (const int*)d_in[1];
        labels = (const int*)d_in[2];  Iin = (const float*)d_in[3];
        Wout = (const float*)d_in[4];  bout = (const float*)d_in[5];
        for (int j = 0; j < 8; j++) { Ws[j] = (const float*)d_in[6 + 2 * j]; Bs[j] = (const float*)d_in[7 + 2 * j]; }
        n_nodes = in_sizes[0] / D_DIM;
    }
    const float *Wq0 = Ws[0], *Wk0 = Ws[1], *Wv0 = Ws[2], *Wo0 = Ws[3];
    const float *Wq1 = Ws[4], *Wk1 = Ws[5], *Wv1 = Ws[6], *Wo1 = Ws[7];
    const float *bq0 = Bs[0], *bk0 = Bs[1], *bv0 = Bs[2], *bo0 = Bs[3];
    const float *bq1 = Bs[4], *bk1 = Bs[5], *bv1 = Bs[6], *bo1 = Bs[7];

    cudaFuncSetAttribute(whatsnet_mma, cudaFuncAttributeMaxDynamicSharedMemorySize, SMEM_TOTAL);

    iq_kernel<<<2, 256>>>(Iin, Wq0, bq0);
    iqb_kernel<<<1, 32>>>(bk0);
    p_kernel<<<8, 256>>>(Wk0);
    wconv_kernel<<<7, 256>>>(Wk0, Wv0, Wq1, Wo0, Wk1, Wv1, Wo1);

    whatsnet_mma<<<E_EDGES * S_MEM / ROWS, NTH, SMEM_TOTAL>>>(
        vfeat, member_idx, labels, Wout, bout,
        bv0, bo0, bq1, bk1, bv1, bo1,
        (float*)d_out, n_nodes, (long long)out_size);
}